// round 12
// baseline (speedup 1.0000x reference)
#include <cuda_runtime.h>
#include <math.h>
#include <stdint.h>

// Problem dims (fixed)
#define BB   128
#define TT   1024
#define DD   512
#define HH   512
#define H3   1536
#define NCLS 2

typedef unsigned long long ull;

// v4 recurrence smem layout: 4 regions x (128 k x 64 rows) + R + reduce
#define REG_B   32768                      // 128k x 64 floats
#define HS_B    (4 * REG_B)                // 128KB
#define RS_OFF  HS_B
#define RS_B    (12 * 512 * 8)             // 48KB paired R (3 gates x 4 colpairs)
#define RED_OFF (RS_OFF + RS_B)
#define RED_B   (128 * 6 * 8)              // 6KB
#define SMEM_DYN (RED_OFF + RED_B)

// ---------------- scratch ----------------------------------------------------
__device__ float  g_xp[(size_t)BB * TT * H3];   // [B*T, 3H], row m = b*T + t
__device__ float2 g_Rp[768 * 512];              // paired Rt: g_Rp[i][k] = (R[k][2i], R[k][2i+1])
__device__ float  g_hT[2][HH * BB];             // hidden, TRANSPOSED [k][r]
__device__ unsigned int g_bar;

// ---------------- f32x2 helpers ---------------------------------------------
__device__ __forceinline__ ull pack2(float a, float b) {
    ull r; asm("mov.b64 %0, {%1, %2};" : "=l"(r) : "f"(a), "f"(b)); return r;
}
__device__ __forceinline__ void unpack2(ull p, float& a, float& b) {
    asm("mov.b64 {%0, %1}, %2;" : "=f"(a), "=f"(b) : "l"(p));
}
__device__ __forceinline__ ull ffma2(ull a, ull b, ull c) {
    ull d; asm("fma.rn.f32x2 %0, %1, %2, %3;" : "=l"(d) : "l"(a), "l"(b), "l"(c)); return d;
}
__device__ __forceinline__ ull addx2(ull a, ull b) {
    ull d; asm("add.rn.f32x2 %0, %1, %2;" : "=l"(d) : "l"(a), "l"(b)); return d;
}
__device__ __forceinline__ void cpa16(uint32_t s, const void* g) {
    asm volatile("cp.async.cg.shared.global [%0], [%1], 16;" :: "r"(s), "l"(g));
}
#define CP_COMMIT() asm volatile("cp.async.commit_group;")
#define CP_WAIT1()  asm volatile("cp.async.wait_group 1;")
#define CP_WAIT0()  asm volatile("cp.async.wait_group 0;")

// ---------------- init -------------------------------------------------------
__global__ void init_kernel() {
    int idx = blockIdx.x * blockDim.x + threadIdx.x;
    if (idx == 0) g_bar = 0u;
    if (idx < BB * HH) g_hT[0][idx] = 0.0f;
}

// ---------------- build paired R: R [H,3H] -> g_Rp [768][512] ----------------
__global__ void build_Rp(const float* __restrict__ R) {
    int idx = blockIdx.x * blockDim.x + threadIdx.x;  // over 768*512
    if (idx < 768 * 512) {
        int i = idx >> 9;        // pair index (0..767), cols 2i,2i+1
        int k = idx & 511;
        g_Rp[idx] = make_float2(R[(size_t)k * H3 + 2 * i], R[(size_t)k * H3 + 2 * i + 1]);
    }
}

// ---------------- GEMM1: xp = x @ W + b_i (f32x2) ----------------------------
#define BM 128
#define BN 128
#define BKK 8
#define TM 8
#define TN 8

__global__ void __launch_bounds__(256, 2)
gemm_xw(const float* __restrict__ A, const float* __restrict__ Bm,
        const float* __restrict__ bias, float* __restrict__ C,
        int M, int N, int K) {
    __shared__ float As[BKK][BM];
    __shared__ float Bs[BKK][BN];

    const int tid = threadIdx.x;
    const int brow = blockIdx.y;
    const int bcol = blockIdx.x;

    const int a_row = tid >> 1;
    const int a_col = (tid & 1) * 4;
    const int b_row = tid >> 5;
    const int b_col = (tid & 31) * 4;

    const int tx = tid & 15;
    const int ty = tid >> 4;

    ull accp[TM][TN / 2];
#pragma unroll
    for (int i = 0; i < TM; ++i)
#pragma unroll
        for (int j = 0; j < TN / 2; ++j) accp[i][j] = 0ull;

    const float* Ab = A + (size_t)(brow * BM) * K;
    const float* Bb = Bm + bcol * BN;

    for (int k0 = 0; k0 < K; k0 += BKK) {
        float4 av = *(const float4*)(Ab + (size_t)a_row * K + k0 + a_col);
        As[a_col + 0][a_row] = av.x;
        As[a_col + 1][a_row] = av.y;
        As[a_col + 2][a_row] = av.z;
        As[a_col + 3][a_row] = av.w;
        float4 bv = *(const float4*)(Bb + (size_t)(k0 + b_row) * N + b_col);
        *(float4*)&Bs[b_row][b_col] = bv;
        __syncthreads();

#pragma unroll
        for (int k = 0; k < BKK; ++k) {
            float ar[TM];
            float4 a0 = *(const float4*)&As[k][ty * TM];
            float4 a1 = *(const float4*)&As[k][ty * TM + 4];
            ar[0]=a0.x; ar[1]=a0.y; ar[2]=a0.z; ar[3]=a0.w;
            ar[4]=a1.x; ar[5]=a1.y; ar[6]=a1.z; ar[7]=a1.w;
            ulonglong2 bq0 = *(const ulonglong2*)&Bs[k][tx * TN];
            ulonglong2 bq1 = *(const ulonglong2*)&Bs[k][tx * TN + 4];
            ull bp0 = bq0.x, bp1 = bq0.y, bp2 = bq1.x, bp3 = bq1.y;
#pragma unroll
            for (int i = 0; i < TM; ++i) {
                ull as = pack2(ar[i], ar[i]);
                accp[i][0] = ffma2(as, bp0, accp[i][0]);
                accp[i][1] = ffma2(as, bp1, accp[i][1]);
                accp[i][2] = ffma2(as, bp2, accp[i][2]);
                accp[i][3] = ffma2(as, bp3, accp[i][3]);
            }
        }
        __syncthreads();
    }

    const int c_col0 = bcol * BN + tx * TN;
    float bsv[TN];
#pragma unroll
    for (int j = 0; j < TN; ++j) bsv[j] = bias[c_col0 + j];

    float* Cb = C + (size_t)(brow * BM + ty * TM) * N + c_col0;
#pragma unroll
    for (int i = 0; i < TM; ++i) {
#pragma unroll
        for (int j = 0; j < TN / 2; ++j) {
            float lo, hi; unpack2(accp[i][j], lo, hi);
            Cb[(size_t)i * N + 2 * j]     = lo + bsv[2 * j];
            Cb[(size_t)i * N + 2 * j + 1] = hi + bsv[2 * j + 1];
        }
    }
}

// ---------------- persistent GRU recurrence (v4: batch-split) ----------------
// 128 CTAs = 64 col-groups (8 cols) x 2 batch halves (64 rows).
// 256 threads: half = tid>>7 reduces k in [half*256, half*256+256);
//   lt = tid&127: cpi = lt>>5 (colpair 0..3), rp = lt&31 (local rows 2rp,2rp+1).
// Each CTA stages ONLY its 64 batch rows: 512k x 64r = 128KB, in 2 commit
// groups (regions 0+1 then 2+3), single-buffered -> 2 waits/step.
// region = part*2 + half holds k in [half*256 + part*128, +128).

__device__ __forceinline__ float fsig(float x)  { return 1.0f / (1.0f + __expf(-x)); }
__device__ __forceinline__ float ftanh(float x) { return 1.0f - 2.0f / (__expf(2.0f * x) + 1.0f); }

// stage one part: region part*2 (k half0) + region part*2+1 (k half1); one commit
__device__ __forceinline__ void stage_part(uint32_t hsS, const float* hcur,
                                           int part, int bh, int tid) {
    int kA = (tid >> 1) + part * 128;          // k for half0 region
    int seg = tid & 1;                          // 32-row segment
    // region part*2: k = kA (in [part*128, part*128+128))
    {
        uint32_t dst = hsS + (uint32_t)((part * 2) * REG_B) + (uint32_t)(((kA - part * 128) << 8) + (seg << 7));
        const char* src = (const char*)hcur + (size_t)kA * 512 + bh * 256 + seg * 128;
#pragma unroll
        for (int j = 0; j < 8; ++j) cpa16(dst + j * 16, src + j * 16);
    }
    // region part*2+1: k = kA + 256
    {
        uint32_t dst = hsS + (uint32_t)((part * 2 + 1) * REG_B) + (uint32_t)(((kA - part * 128) << 8) + (seg << 7));
        const char* src = (const char*)hcur + (size_t)(kA + 256) * 512 + bh * 256 + seg * 128;
#pragma unroll
        for (int j = 0; j < 8; ++j) cpa16(dst + j * 16, src + j * 16);
    }
    CP_COMMIT();
}

__global__ void __launch_bounds__(256, 1)
gru_recurrent(const float* __restrict__ xp, const float* __restrict__ brv) {
    extern __shared__ char sm[];
    float*  hs  = (float*)sm;
    float2* Rs  = (float2*)(sm + RS_OFF);
    ull*    red = (ull*)(sm + RED_OFF);

    const int tid  = threadIdx.x;
    const int half = tid >> 7;
    const int lt   = tid & 127;
    const int cpi  = lt >> 5;          // 0..3 (colpair within 8 cols)
    const int rp   = lt & 31;          // 0..31 (local row pair)
    const int r0l  = rp * 2;           // local row 0..62
    const int blk  = blockIdx.x;
    const int cg   = blk >> 1;         // col-group 0..63
    const int bh   = blk & 1;          // batch half
    const int c0   = cg * 8 + 2 * cpi;
    const int gr0  = bh * 64 + r0l;    // global row

    // persistent paired R: 12 pair-rows (gate*4 + cpi) x 512 k
    for (int i = tid; i < 12 * 512; i += 256) {
        int L = i >> 9;
        int k = i & 511;
        int gate = L >> 2, cp = L & 3;
        int gp = gate * 256 + cg * 4 + cp;
        Rs[(size_t)L * 512 + k] = g_Rp[(size_t)gp * 512 + k];
    }

    const float2 bz2 = *(const float2*)(brv + c0);
    const float2 br2 = *(const float2*)(brv + HH + c0);
    const float2 bh2 = *(const float2*)(brv + 2 * HH + c0);

    const unsigned nCTA = gridDim.x;
    uint32_t hsS = (uint32_t)__cvta_generic_to_shared(hs);
    __syncthreads();

    for (int t = 0; t < TT; ++t) {
        const float* hcur = g_hT[t & 1];
        float* hnx = g_hT[(t + 1) & 1];

        // prefetch xp gate inputs + h_old from global (latency overlaps staging)
        float2 xzp[2], xrp[2], xhp[2];
        float2 ho0, ho1;
#pragma unroll
        for (int rr = 0; rr < 2; ++rr) {
            const float* xb = xp + ((size_t)(gr0 + rr) * TT + t) * H3;
            xzp[rr] = *(const float2*)(xb + c0);
            xrp[rr] = *(const float2*)(xb + HH + c0);
            xhp[rr] = *(const float2*)(xb + 2 * HH + c0);
        }
        ho0 = *(const float2*)(hcur + (size_t)c0 * BB + gr0);        // col c0
        ho1 = *(const float2*)(hcur + (size_t)(c0 + 1) * BB + gr0);  // col c0+1

        // stage both parts up-front (disjoint regions, single-buffered)
        stage_part(hsS, hcur, 0, bh, tid);
        stage_part(hsS, hcur, 1, bh, tid);

        ull az0 = 0, az1 = 0, ar0 = 0, ar1 = 0, ah0 = 0, ah1 = 0;

#pragma unroll
        for (int p = 0; p < 2; ++p) {
            if (p == 0) { CP_WAIT1(); } else { CP_WAIT0(); }
            __syncthreads();

            const float* hb = hs + (size_t)((p * 2 + half) * (REG_B / 4));
            const int kg = half * 256 + p * 128;
            const float2* Rz = Rs + (size_t)(0 + cpi) * 512 + kg;
            const float2* Rr = Rs + (size_t)(4 + cpi) * 512 + kg;
            const float2* Rh = Rs + (size_t)(8 + cpi) * 512 + kg;

#pragma unroll 8
            for (int kk = 0; kk < 128; kk += 2) {
                ull hp0 = *(const ull*)(hb + (size_t)kk * 64 + r0l);
                ull hp1 = *(const ull*)(hb + (size_t)(kk + 1) * 64 + r0l);
                float h00, h01; unpack2(hp0, h00, h01);
                float h10, h11; unpack2(hp1, h10, h11);
                ull s00 = pack2(h00, h00), s01 = pack2(h01, h01);
                ull s10 = pack2(h10, h10), s11 = pack2(h11, h11);

                ulonglong2 vz = *(const ulonglong2*)(Rz + kk);
                ulonglong2 vr = *(const ulonglong2*)(Rr + kk);
                ulonglong2 vh = *(const ulonglong2*)(Rh + kk);

                az0 = ffma2(s00, vz.x, az0);  az1 = ffma2(s01, vz.x, az1);
                ar0 = ffma2(s00, vr.x, ar0);  ar1 = ffma2(s01, vr.x, ar1);
                ah0 = ffma2(s00, vh.x, ah0);  ah1 = ffma2(s01, vh.x, ah1);
                az0 = ffma2(s10, vz.y, az0);  az1 = ffma2(s11, vz.y, az1);
                ar0 = ffma2(s10, vr.y, ar0);  ar1 = ffma2(s11, vr.y, ar1);
                ah0 = ffma2(s10, vh.y, ah0);  ah1 = ffma2(s11, vh.y, ah1);
            }
        }

        // K-split reduction: half 1 -> smem, half 0 accumulates
        if (half) {
            ull* rd = red + (size_t)lt * 6;
            rd[0] = az0; rd[1] = az1; rd[2] = ar0;
            rd[3] = ar1; rd[4] = ah0; rd[5] = ah1;
        }
        __syncthreads();
        if (!half) {
            const ull* rd = red + (size_t)lt * 6;
            az0 = addx2(az0, rd[0]); az1 = addx2(az1, rd[1]);
            ar0 = addx2(ar0, rd[2]); ar1 = addx2(ar1, rd[3]);
            ah0 = addx2(ah0, rd[4]); ah1 = addx2(ah1, rd[5]);

            float azc[2][2], arc[2][2], ahc[2][2];
            unpack2(az0, azc[0][0], azc[0][1]);
            unpack2(az1, azc[1][0], azc[1][1]);
            unpack2(ar0, arc[0][0], arc[0][1]);
            unpack2(ar1, arc[1][0], arc[1][1]);
            unpack2(ah0, ahc[0][0], ahc[0][1]);
            unpack2(ah1, ahc[1][0], ahc[1][1]);

            float hold[2][2] = {{ho0.x, ho1.x}, {ho0.y, ho1.y}};
            float bzv[2]  = {bz2.x, bz2.y};
            float brvv[2] = {br2.x, br2.y};
            float bhv[2]  = {bh2.x, bh2.y};
            float hnew[2][2];
#pragma unroll
            for (int rr = 0; rr < 2; ++rr) {
                float xzv[2] = {xzp[rr].x, xzp[rr].y};
                float xrv[2] = {xrp[rr].x, xrp[rr].y};
                float xhv[2] = {xhp[rr].x, xhp[rr].y};
#pragma unroll
                for (int cc = 0; cc < 2; ++cc) {
                    float z  = fsig(xzv[cc] + azc[rr][cc] + bzv[cc]);
                    float rg = fsig(xrv[cc] + arc[rr][cc] + brvv[cc]);
                    float hv = ftanh(xhv[cc] + rg * (ahc[rr][cc] + bhv[cc]));
                    hnew[rr][cc] = z * hold[rr][cc] + (1.0f - z) * hv;
                }
            }
            *(float2*)(hnx + (size_t)c0 * BB + gr0)       = make_float2(hnew[0][0], hnew[1][0]);
            *(float2*)(hnx + (size_t)(c0 + 1) * BB + gr0) = make_float2(hnew[0][1], hnew[1][1]);

            __threadfence();   // only storing threads need the release
        }

        // grid barrier
        __syncthreads();
        if (tid == 0) {
            atomicAdd(&g_bar, 1u);
            unsigned target = nCTA * (unsigned)(t + 1);
            while (*(volatile unsigned*)&g_bar < target) { }
            __threadfence();
        }
        __syncthreads();
    }
}

// ---------------- final: logits = h_last @ Wf + bf ---------------------------
__global__ void final_logits(const float* __restrict__ Wf,
                             const float* __restrict__ bf,
                             float* __restrict__ out) {
    int tid = threadIdx.x;          // 256 threads: r = tid>>1, c = tid&1
    int r = tid >> 1;
    int c = tid & 1;
    const float* h = g_hT[TT & 1];  // T even -> buffer 0, layout [k][r]
    float acc = 0.0f;
    for (int k = 0; k < HH; ++k)
        acc += h[(size_t)k * BB + r] * Wf[k * NCLS + c];
    out[r * NCLS + c] = acc + bf[c];
}

// ---------------- launch -----------------------------------------------------
extern "C" void kernel_launch(void* const* d_in, const int* in_sizes, int n_in,
                              void* d_out, int out_size) {
    const float* x   = (const float*)d_in[0];
    const float* W   = (const float*)d_in[1];
    const float* R   = (const float*)d_in[2];
    const float* b_i = (const float*)d_in[3];
    const float* b_r = (const float*)d_in[4];
    const float* Wf  = (const float*)d_in[5];
    const float* bf  = (const float*)d_in[6];
    float* out = (float*)d_out;

    float* xp;
    cudaGetSymbolAddress((void**)&xp, g_xp);

    static bool attr_set = false;
    if (!attr_set) {
        cudaFuncSetAttribute(gru_recurrent,
                             cudaFuncAttributeMaxDynamicSharedMemorySize, SMEM_DYN);
        attr_set = true;
    }

    init_kernel<<<(BB * HH + 255) / 256, 256>>>();
    build_Rp<<<(768 * 512 + 255) / 256, 256>>>(R);
    {
        dim3 grid(H3 / BN, (BB * TT) / BM);
        gemm_xw<<<grid, 256>>>(x, W, b_i, xp, BB * TT, H3, DD);
    }
    gru_recurrent<<<128, 256, SMEM_DYN>>>(xp, b_r);
    final_logits<<<1, 256>>>(Wf, bf, out);
}

// round 13
// speedup vs baseline: 1.2257x; 1.2257x over previous
#include <cuda_runtime.h>
#include <math.h>
#include <stdint.h>

// Problem dims (fixed)
#define BB   128
#define TT   1024
#define DD   512
#define HH   512
#define H3   1536
#define NCLS 2

typedef unsigned long long ull;

// v5 recurrence smem: contiguous h slice [512k][64r] + R + reduce
#define HS_B    131072                     // 512 * 64 * 4
#define RS_OFF  HS_B
#define RS_B    (12 * 512 * 8)             // 48KB paired R
#define RED_OFF (RS_OFF + RS_B)
#define RED_B   (128 * 6 * 8)              // 6KB
#define SMEM_DYN (RED_OFF + RED_B)

// ---------------- scratch ----------------------------------------------------
__device__ float  g_xp[(size_t)BB * TT * H3];   // [B*T, 3H], row m = b*T + t
__device__ float2 g_Rp[768 * 512];              // paired Rt
__device__ float  g_h2[2][2][512][64];          // [buf][bh][k][local row]
__device__ unsigned int g_bar;

// ---------------- f32x2 helpers ---------------------------------------------
__device__ __forceinline__ ull pack2(float a, float b) {
    ull r; asm("mov.b64 %0, {%1, %2};" : "=l"(r) : "f"(a), "f"(b)); return r;
}
__device__ __forceinline__ void unpack2(ull p, float& a, float& b) {
    asm("mov.b64 {%0, %1}, %2;" : "=f"(a), "=f"(b) : "l"(p));
}
__device__ __forceinline__ ull ffma2(ull a, ull b, ull c) {
    ull d; asm("fma.rn.f32x2 %0, %1, %2, %3;" : "=l"(d) : "l"(a), "l"(b), "l"(c)); return d;
}
__device__ __forceinline__ ull addx2(ull a, ull b) {
    ull d; asm("add.rn.f32x2 %0, %1, %2;" : "=l"(d) : "l"(a), "l"(b)); return d;
}

// ---------------- bulk-async + mbarrier helpers ------------------------------
__device__ __forceinline__ void mbar_init(uint32_t a, uint32_t cnt) {
    asm volatile("mbarrier.init.shared.b64 [%0], %1;" :: "r"(a), "r"(cnt) : "memory");
}
__device__ __forceinline__ void mbar_expect_tx(uint32_t a, uint32_t tx) {
    asm volatile("mbarrier.arrive.expect_tx.shared.b64 _, [%0], %1;"
                 :: "r"(a), "r"(tx) : "memory");
}
__device__ __forceinline__ void mbar_wait(uint32_t a, uint32_t parity) {
    asm volatile(
        "{\n\t"
        ".reg .pred P;\n\t"
        "WL%=:\n\t"
        "mbarrier.try_wait.parity.shared.b64 P, [%0], %1;\n\t"
        "@!P bra WL%=;\n\t"
        "}"
        :: "r"(a), "r"(parity) : "memory");
}
__device__ __forceinline__ void bulk_g2s(uint32_t dst, const void* src,
                                         uint32_t bytes, uint32_t mbar) {
    ull g;
    asm volatile("cvta.to.global.u64 %0, %1;" : "=l"(g) : "l"(src));
    asm volatile(
        "cp.async.bulk.shared::cluster.global.mbarrier::complete_tx::bytes "
        "[%0], [%1], %2, [%3];"
        :: "r"(dst), "l"(g), "r"(bytes), "r"(mbar) : "memory");
}
#define FENCE_PROXY() asm volatile("fence.proxy.async.shared::cta;" ::: "memory")

// ---------------- init -------------------------------------------------------
__global__ void init_kernel() {
    int idx = blockIdx.x * blockDim.x + threadIdx.x;
    if (idx == 0) g_bar = 0u;
    if (idx < 2 * 512 * 64) ((float*)g_h2[0])[idx] = 0.0f;
}

// ---------------- build paired R: R [H,3H] -> g_Rp [768][512] ----------------
__global__ void build_Rp(const float* __restrict__ R) {
    int idx = blockIdx.x * blockDim.x + threadIdx.x;
    if (idx < 768 * 512) {
        int i = idx >> 9;
        int k = idx & 511;
        g_Rp[idx] = make_float2(R[(size_t)k * H3 + 2 * i], R[(size_t)k * H3 + 2 * i + 1]);
    }
}

// ---------------- GEMM1: xp = x @ W + b_i (f32x2, unchanged) ------------------
#define BM 128
#define BN 128
#define BKK 8
#define TM 8
#define TN 8

__global__ void __launch_bounds__(256, 2)
gemm_xw(const float* __restrict__ A, const float* __restrict__ Bm,
        const float* __restrict__ bias, float* __restrict__ C,
        int M, int N, int K) {
    __shared__ float As[BKK][BM];
    __shared__ float Bs[BKK][BN];

    const int tid = threadIdx.x;
    const int brow = blockIdx.y;
    const int bcol = blockIdx.x;

    const int a_row = tid >> 1;
    const int a_col = (tid & 1) * 4;
    const int b_row = tid >> 5;
    const int b_col = (tid & 31) * 4;

    const int tx = tid & 15;
    const int ty = tid >> 4;

    ull accp[TM][TN / 2];
#pragma unroll
    for (int i = 0; i < TM; ++i)
#pragma unroll
        for (int j = 0; j < TN / 2; ++j) accp[i][j] = 0ull;

    const float* Ab = A + (size_t)(brow * BM) * K;
    const float* Bb = Bm + bcol * BN;

    for (int k0 = 0; k0 < K; k0 += BKK) {
        float4 av = *(const float4*)(Ab + (size_t)a_row * K + k0 + a_col);
        As[a_col + 0][a_row] = av.x;
        As[a_col + 1][a_row] = av.y;
        As[a_col + 2][a_row] = av.z;
        As[a_col + 3][a_row] = av.w;
        float4 bv = *(const float4*)(Bb + (size_t)(k0 + b_row) * N + b_col);
        *(float4*)&Bs[b_row][b_col] = bv;
        __syncthreads();

#pragma unroll
        for (int k = 0; k < BKK; ++k) {
            float ar[TM];
            float4 a0 = *(const float4*)&As[k][ty * TM];
            float4 a1 = *(const float4*)&As[k][ty * TM + 4];
            ar[0]=a0.x; ar[1]=a0.y; ar[2]=a0.z; ar[3]=a0.w;
            ar[4]=a1.x; ar[5]=a1.y; ar[6]=a1.z; ar[7]=a1.w;
            ulonglong2 bq0 = *(const ulonglong2*)&Bs[k][tx * TN];
            ulonglong2 bq1 = *(const ulonglong2*)&Bs[k][tx * TN + 4];
            ull bp0 = bq0.x, bp1 = bq0.y, bp2 = bq1.x, bp3 = bq1.y;
#pragma unroll
            for (int i = 0; i < TM; ++i) {
                ull as = pack2(ar[i], ar[i]);
                accp[i][0] = ffma2(as, bp0, accp[i][0]);
                accp[i][1] = ffma2(as, bp1, accp[i][1]);
                accp[i][2] = ffma2(as, bp2, accp[i][2]);
                accp[i][3] = ffma2(as, bp3, accp[i][3]);
            }
        }
        __syncthreads();
    }

    const int c_col0 = bcol * BN + tx * TN;
    float bsv[TN];
#pragma unroll
    for (int j = 0; j < TN; ++j) bsv[j] = bias[c_col0 + j];

    float* Cb = C + (size_t)(brow * BM + ty * TM) * N + c_col0;
#pragma unroll
    for (int i = 0; i < TM; ++i) {
#pragma unroll
        for (int j = 0; j < TN / 2; ++j) {
            float lo, hi; unpack2(accp[i][j], lo, hi);
            Cb[(size_t)i * N + 2 * j]     = lo + bsv[2 * j];
            Cb[(size_t)i * N + 2 * j + 1] = hi + bsv[2 * j + 1];
        }
    }
}

// ---------------- persistent GRU recurrence (v5: bulk-async staging) ----------
// 128 CTAs = 64 col-groups x 2 batch halves. 256 threads:
//   half = tid>>7 (K half), lt = tid&127, cpi = lt>>5, rp = lt&31.
// h global layout [buf][bh][k][64 local rows]: CTA slice is contiguous 128KB,
// staged per step by TWO cp.async.bulk copies (64KB each, one mbarrier each).
// h_old carried in registers across steps.

__device__ __forceinline__ float fsig(float x)  { return 1.0f / (1.0f + __expf(-x)); }
__device__ __forceinline__ float ftanh(float x) { return 1.0f - 2.0f / (__expf(2.0f * x) + 1.0f); }

__global__ void __launch_bounds__(256, 1)
gru_recurrent(const float* __restrict__ xp, const float* __restrict__ brv) {
    extern __shared__ char sm[];
    float*  hs  = (float*)sm;                 // [512][64]
    float2* Rs  = (float2*)(sm + RS_OFF);
    ull*    red = (ull*)(sm + RED_OFF);
    __shared__ ull smb[2];

    const int tid  = threadIdx.x;
    const int half = tid >> 7;
    const int lt   = tid & 127;
    const int cpi  = lt >> 5;          // 0..3
    const int rp   = lt & 31;          // 0..31
    const int r0l  = rp * 2;           // local row
    const int blk  = blockIdx.x;
    const int cg   = blk >> 1;         // col-group
    const int bh   = blk & 1;          // batch half
    const int c0   = cg * 8 + 2 * cpi;
    const int gr0  = bh * 64 + r0l;    // global row

    uint32_t mbA = (uint32_t)__cvta_generic_to_shared(&smb[0]);
    uint32_t mbB = (uint32_t)__cvta_generic_to_shared(&smb[1]);
    uint32_t hsS = (uint32_t)__cvta_generic_to_shared(hs);
    if (tid == 0) { mbar_init(mbA, 1); mbar_init(mbB, 1); }

    // persistent paired R: 12 pair-rows (gate*4 + cpi) x 512 k
    for (int i = tid; i < 12 * 512; i += 256) {
        int L = i >> 9;
        int k = i & 511;
        int gate = L >> 2, cp = L & 3;
        int gp = gate * 256 + cg * 4 + cp;
        Rs[(size_t)L * 512 + k] = g_Rp[(size_t)gp * 512 + k];
    }

    const float2 bz2 = *(const float2*)(brv + c0);
    const float2 br2 = *(const float2*)(brv + HH + c0);
    const float2 bh2 = *(const float2*)(brv + 2 * HH + c0);

    // h_old carried in registers (h0 = 0)
    float hprev[2][2] = {{0.0f, 0.0f}, {0.0f, 0.0f}};

    const unsigned nCTA = gridDim.x;
    const uint32_t mywait = half ? mbB : mbA;
    __syncthreads();

    for (int t = 0; t < TT; ++t) {
        const float* hcur = (const float*)g_h2[t & 1][bh];
        float* hnx = (float*)g_h2[(t + 1) & 1][bh];

        // tid0 kicks off both bulk copies (slice is contiguous)
        if (tid == 0) {
            FENCE_PROXY();
            mbar_expect_tx(mbA, 65536u);
            bulk_g2s(hsS, hcur, 65536u, mbA);
            mbar_expect_tx(mbB, 65536u);
            bulk_g2s(hsS + 65536u, hcur + 16384, 65536u, mbB);
        }

        // prefetch xp gate inputs (DRAM latency overlaps bulk copy + compute)
        float2 xzp[2], xrp[2], xhp[2];
#pragma unroll
        for (int rr = 0; rr < 2; ++rr) {
            const float* xb = xp + ((size_t)(gr0 + rr) * TT + t) * H3;
            xzp[rr] = *(const float2*)(xb + c0);
            xrp[rr] = *(const float2*)(xb + HH + c0);
            xhp[rr] = *(const float2*)(xb + 2 * HH + c0);
        }

        // wait for this half's 64KB
        mbar_wait(mywait, (uint32_t)(t & 1));

        ull az0 = 0, az1 = 0, ar0 = 0, ar1 = 0, ah0 = 0, ah1 = 0;

        const float* hb = hs + (size_t)(half * 256) * 64;
        const int kg = half * 256;
        const float2* Rz = Rs + (size_t)(0 + cpi) * 512 + kg;
        const float2* Rr = Rs + (size_t)(4 + cpi) * 512 + kg;
        const float2* Rh = Rs + (size_t)(8 + cpi) * 512 + kg;

#pragma unroll 8
        for (int kk = 0; kk < 256; kk += 2) {
            ull hp0 = *(const ull*)(hb + (size_t)kk * 64 + r0l);
            ull hp1 = *(const ull*)(hb + (size_t)(kk + 1) * 64 + r0l);
            float h00, h01; unpack2(hp0, h00, h01);
            float h10, h11; unpack2(hp1, h10, h11);
            ull s00 = pack2(h00, h00), s01 = pack2(h01, h01);
            ull s10 = pack2(h10, h10), s11 = pack2(h11, h11);

            ulonglong2 vz = *(const ulonglong2*)(Rz + kk);
            ulonglong2 vr = *(const ulonglong2*)(Rr + kk);
            ulonglong2 vh = *(const ulonglong2*)(Rh + kk);

            az0 = ffma2(s00, vz.x, az0);  az1 = ffma2(s01, vz.x, az1);
            ar0 = ffma2(s00, vr.x, ar0);  ar1 = ffma2(s01, vr.x, ar1);
            ah0 = ffma2(s00, vh.x, ah0);  ah1 = ffma2(s01, vh.x, ah1);
            az0 = ffma2(s10, vz.y, az0);  az1 = ffma2(s11, vz.y, az1);
            ar0 = ffma2(s10, vr.y, ar0);  ar1 = ffma2(s11, vr.y, ar1);
            ah0 = ffma2(s10, vh.y, ah0);  ah1 = ffma2(s11, vh.y, ah1);
        }

        // K-split reduction: half 1 -> smem, half 0 accumulates + epilogue
        if (half) {
            ull* rd = red + (size_t)lt * 6;
            rd[0] = az0; rd[1] = az1; rd[2] = ar0;
            rd[3] = ar1; rd[4] = ah0; rd[5] = ah1;
        }
        __syncthreads();
        if (!half) {
            const ull* rd = red + (size_t)lt * 6;
            az0 = addx2(az0, rd[0]); az1 = addx2(az1, rd[1]);
            ar0 = addx2(ar0, rd[2]); ar1 = addx2(ar1, rd[3]);
            ah0 = addx2(ah0, rd[4]); ah1 = addx2(ah1, rd[5]);

            float azc[2][2], arc[2][2], ahc[2][2];
            unpack2(az0, azc[0][0], azc[0][1]);
            unpack2(az1, azc[1][0], azc[1][1]);
            unpack2(ar0, arc[0][0], arc[0][1]);
            unpack2(ar1, arc[1][0], arc[1][1]);
            unpack2(ah0, ahc[0][0], ahc[0][1]);
            unpack2(ah1, ahc[1][0], ahc[1][1]);

            float bzv[2]  = {bz2.x, bz2.y};
            float brvv[2] = {br2.x, br2.y};
            float bhv[2]  = {bh2.x, bh2.y};
#pragma unroll
            for (int rr = 0; rr < 2; ++rr) {
                float xzv[2] = {xzp[rr].x, xzp[rr].y};
                float xrv[2] = {xrp[rr].x, xrp[rr].y};
                float xhv[2] = {xhp[rr].x, xhp[rr].y};
#pragma unroll
                for (int cc = 0; cc < 2; ++cc) {
                    float z  = fsig(xzv[cc] + azc[rr][cc] + bzv[cc]);
                    float rg = fsig(xrv[cc] + arc[rr][cc] + brvv[cc]);
                    float hv = ftanh(xhv[cc] + rg * (ahc[rr][cc] + bhv[cc]));
                    hprev[rr][cc] = z * hprev[rr][cc] + (1.0f - z) * hv;
                }
            }
            // store to [bh][k=c0][local rows]
            *(float2*)(hnx + (size_t)c0 * 64 + r0l)       = make_float2(hprev[0][0], hprev[1][0]);
            *(float2*)(hnx + (size_t)(c0 + 1) * 64 + r0l) = make_float2(hprev[0][1], hprev[1][1]);
            __threadfence();
        }

        // grid barrier
        __syncthreads();
        if (tid == 0) {
            atomicAdd(&g_bar, 1u);
            unsigned target = nCTA * (unsigned)(t + 1);
            while (*(volatile unsigned*)&g_bar < target) { }
            __threadfence();
        }
        __syncthreads();
    }
}

// ---------------- final: logits = h_last @ Wf + bf ---------------------------
__global__ void final_logits(const float* __restrict__ Wf,
                             const float* __restrict__ bf,
                             float* __restrict__ out) {
    int tid = threadIdx.x;          // 256 threads: r = tid>>1, c = tid&1
    int r = tid >> 1;
    int c = tid & 1;
    const float* hsl = (const float*)g_h2[TT & 1][r >> 6];   // [k][64]
    int rl = r & 63;
    float acc = 0.0f;
    for (int k = 0; k < HH; ++k)
        acc += hsl[(size_t)k * 64 + rl] * Wf[k * NCLS + c];
    out[r * NCLS + c] = acc + bf[c];
}

// ---------------- launch -----------------------------------------------------
extern "C" void kernel_launch(void* const* d_in, const int* in_sizes, int n_in,
                              void* d_out, int out_size) {
    const float* x   = (const float*)d_in[0];
    const float* W   = (const float*)d_in[1];
    const float* R   = (const float*)d_in[2];
    const float* b_i = (const float*)d_in[3];
    const float* b_r = (const float*)d_in[4];
    const float* Wf  = (const float*)d_in[5];
    const float* bf  = (const float*)d_in[6];
    float* out = (float*)d_out;

    float* xp;
    cudaGetSymbolAddress((void**)&xp, g_xp);

    static bool attr_set = false;
    if (!attr_set) {
        cudaFuncSetAttribute(gru_recurrent,
                             cudaFuncAttributeMaxDynamicSharedMemorySize, SMEM_DYN);
        attr_set = true;
    }

    init_kernel<<<(2 * 512 * 64 + 255) / 256, 256>>>();
    build_Rp<<<(768 * 512 + 255) / 256, 256>>>(R);
    {
        dim3 grid(H3 / BN, (BB * TT) / BM);
        gemm_xw<<<grid, 256>>>(x, W, b_i, xp, BB * TT, H3, DD);
    }
    gru_recurrent<<<128, 256, SMEM_DYN>>>(xp, b_r);
    final_logits<<<1, 256>>>(Wf, bf, out);
}

// round 14
// speedup vs baseline: 1.3902x; 1.1342x over previous
#include <cuda_runtime.h>
#include <math.h>
#include <stdint.h>

// Problem dims (fixed)
#define BB   128
#define TT   1024
#define DD   512
#define HH   512
#define H3   1536
#define NCLS 2

typedef unsigned long long ull;

// v5 recurrence smem: contiguous h slice [512k][64r] + R + reduce
#define HS_B    131072                     // 512 * 64 * 4
#define RS_OFF  HS_B
#define RS_B    (12 * 512 * 8)             // 48KB paired R
#define RED_OFF (RS_OFF + RS_B)
#define RED_B   (128 * 6 * 8)              // 6KB
#define SMEM_DYN (RED_OFF + RED_B)

// GEMM1 (tf32 mma) smem: As[2][128][36] + Bh[2][32][136] + Bl[2][32][136]
#define AS_STR  36
#define BS_STR  136
#define AS_FL   (2 * 128 * AS_STR)         // 9216 floats
#define BH_FL   (2 * 32 * BS_STR)          // 8704
#define SMEMG   ((AS_FL + 2 * BH_FL) * 4)  // 106496 bytes

// ---------------- scratch ----------------------------------------------------
__device__ float  g_xp[(size_t)BB * TT * H3];   // [B*T, 3H], row m = b*T + t
__device__ float2 g_Rp[768 * 512];              // paired Rt
__device__ float  g_h2[2][2][512][64];          // [buf][bh][k][local row]
__device__ float  g_Whi[DD * H3];               // tf32-rounded W
__device__ float  g_Wlo[DD * H3];               // tf32 residual
__device__ unsigned int g_bar;

// ---------------- f32x2 helpers ---------------------------------------------
__device__ __forceinline__ ull pack2(float a, float b) {
    ull r; asm("mov.b64 %0, {%1, %2};" : "=l"(r) : "f"(a), "f"(b)); return r;
}
__device__ __forceinline__ void unpack2(ull p, float& a, float& b) {
    asm("mov.b64 {%0, %1}, %2;" : "=f"(a), "=f"(b) : "l"(p));
}
__device__ __forceinline__ ull ffma2(ull a, ull b, ull c) {
    ull d; asm("fma.rn.f32x2 %0, %1, %2, %3;" : "=l"(d) : "l"(a), "l"(b), "l"(c)); return d;
}
__device__ __forceinline__ ull addx2(ull a, ull b) {
    ull d; asm("add.rn.f32x2 %0, %1, %2;" : "=l"(d) : "l"(a), "l"(b)); return d;
}

// ---------------- tf32 helpers -----------------------------------------------
__device__ __forceinline__ uint32_t cvt_tf32(float v) {
    uint32_t r; asm("cvt.rna.tf32.f32 %0, %1;" : "=r"(r) : "f"(v)); return r;
}
#define MMA_TF32(d, a0, a1, a2, a3, b0, b1) \
    asm volatile("mma.sync.aligned.m16n8k8.row.col.f32.tf32.tf32.f32 " \
        "{%0,%1,%2,%3}, {%4,%5,%6,%7}, {%8,%9}, {%0,%1,%2,%3};" \
        : "+f"((d)[0]), "+f"((d)[1]), "+f"((d)[2]), "+f"((d)[3]) \
        : "r"(a0), "r"(a1), "r"(a2), "r"(a3), "r"(b0), "r"(b1))

// ---------------- bulk-async + mbarrier helpers ------------------------------
__device__ __forceinline__ void mbar_init(uint32_t a, uint32_t cnt) {
    asm volatile("mbarrier.init.shared.b64 [%0], %1;" :: "r"(a), "r"(cnt) : "memory");
}
__device__ __forceinline__ void mbar_expect_tx(uint32_t a, uint32_t tx) {
    asm volatile("mbarrier.arrive.expect_tx.shared.b64 _, [%0], %1;"
                 :: "r"(a), "r"(tx) : "memory");
}
__device__ __forceinline__ void mbar_wait(uint32_t a, uint32_t parity) {
    asm volatile(
        "{\n\t"
        ".reg .pred P;\n\t"
        "WL%=:\n\t"
        "mbarrier.try_wait.parity.shared.b64 P, [%0], %1;\n\t"
        "@!P bra WL%=;\n\t"
        "}"
        :: "r"(a), "r"(parity) : "memory");
}
__device__ __forceinline__ void bulk_g2s(uint32_t dst, const void* src,
                                         uint32_t bytes, uint32_t mbar) {
    ull g;
    asm volatile("cvta.to.global.u64 %0, %1;" : "=l"(g) : "l"(src));
    asm volatile(
        "cp.async.bulk.shared::cluster.global.mbarrier::complete_tx::bytes "
        "[%0], [%1], %2, [%3];"
        :: "r"(dst), "l"(g), "r"(bytes), "r"(mbar) : "memory");
}
#define FENCE_PROXY() asm volatile("fence.proxy.async.shared::cta;" ::: "memory")

// ---------------- init -------------------------------------------------------
__global__ void init_kernel() {
    int idx = blockIdx.x * blockDim.x + threadIdx.x;
    if (idx == 0) g_bar = 0u;
    if (idx < 2 * 512 * 64) ((float*)g_h2[0])[idx] = 0.0f;
}

// ---------------- build paired R: R [H,3H] -> g_Rp [768][512] ----------------
__global__ void build_Rp(const float* __restrict__ R) {
    int idx = blockIdx.x * blockDim.x + threadIdx.x;
    if (idx < 768 * 512) {
        int i = idx >> 9;
        int k = idx & 511;
        g_Rp[idx] = make_float2(R[(size_t)k * H3 + 2 * i], R[(size_t)k * H3 + 2 * i + 1]);
    }
}

// ---------------- build W hi/lo tf32 split -----------------------------------
__global__ void build_Whl(const float* __restrict__ W) {
    int idx = blockIdx.x * blockDim.x + threadIdx.x;
    if (idx < DD * H3) {
        float v = W[idx];
        uint32_t h = cvt_tf32(v);
        float hf = __uint_as_float(h);
        g_Whi[idx] = hf;
        g_Wlo[idx] = __uint_as_float(cvt_tf32(v - hf));
    }
}

// ---------------- GEMM1: xp = x @ W + b_i via 3xTF32 mma.sync ----------------
// M=131072, N=1536, K=512. Block tile 128x128, 256 thr = 8 warps (4M x 2N),
// warp tile 32x64 = 2 m16 x 8 n8 mma tiles. K-block 32, double-buffered smem,
// register-pipelined global staging, one syncthreads per k-block.
__global__ void __launch_bounds__(256, 1)
gemm_tf32(const float* __restrict__ A, const float* __restrict__ bias,
          float* __restrict__ C) {
    extern __shared__ float sg[];
    float* As = sg;                       // [2][128][AS_STR]
    float* Bh = sg + AS_FL;               // [2][32][BS_STR]
    float* Bl = Bh + BH_FL;               // [2][32][BS_STR]

    const int tid  = threadIdx.x;
    const int lane = tid & 31;
    const int wid  = tid >> 5;
    const int wm   = wid & 3;             // M quadrant
    const int wn   = wid >> 2;            // N half
    const int g    = lane >> 2;           // 0..7
    const int tg   = lane & 3;            // 0..3
    const int m0   = blockIdx.y * 128;
    const int n0   = blockIdx.x * 128;

    const float* Whi = g_Whi;
    const float* Wlo = g_Wlo;

    float acc[2][8][4];
#pragma unroll
    for (int mt = 0; mt < 2; ++mt)
#pragma unroll
        for (int nt = 0; nt < 8; ++nt)
#pragma unroll
            for (int i = 0; i < 4; ++i) acc[mt][nt][i] = 0.0f;

    float4 ra[4], rbh[4], rbl[4];

    // ---- staging helpers (register pipeline) ----
    auto ldg_block = [&](int kb) {
        const int kbase = kb * 32;
#pragma unroll
        for (int i = 0; i < 4; ++i) {
            int f = tid + i * 256;             // 1024 float4: A tile 128r x 32k
            int row = f >> 3, kq = f & 7;
            ra[i] = *(const float4*)(A + (size_t)(m0 + row) * DD + kbase + kq * 4);
        }
#pragma unroll
        for (int i = 0; i < 4; ++i) {
            int f = tid + i * 256;             // 1024 float4: B tiles 32k x 128n
            int kr = f >> 5, nq = f & 31;
            size_t off = (size_t)(kbase + kr) * H3 + n0 + nq * 4;
            rbh[i] = *(const float4*)(Whi + off);
            rbl[i] = *(const float4*)(Wlo + off);
        }
    };
    auto sts_block = [&](int buf) {
        float* as = As + buf * 128 * AS_STR;
        float* bh = Bh + buf * 32 * BS_STR;
        float* bl = Bl + buf * 32 * BS_STR;
#pragma unroll
        for (int i = 0; i < 4; ++i) {
            int f = tid + i * 256;
            int row = f >> 3, kq = f & 7;
            *(float4*)(as + row * AS_STR + kq * 4) = ra[i];
        }
#pragma unroll
        for (int i = 0; i < 4; ++i) {
            int f = tid + i * 256;
            int kr = f >> 5, nq = f & 31;
            *(float4*)(bh + kr * BS_STR + nq * 4) = rbh[i];
            *(float4*)(bl + kr * BS_STR + nq * 4) = rbl[i];
        }
    };
    auto compute = [&](int buf) {
        const float* as = As + buf * 128 * AS_STR;
        const float* bh = Bh + buf * 32 * BS_STR;
        const float* bl = Bl + buf * 32 * BS_STR;
#pragma unroll
        for (int ks = 0; ks < 32; ks += 8) {
            // B fragments (hi + lo), 8 n-tiles
            uint32_t bh0[8], bh1[8], bl0[8], bl1[8];
#pragma unroll
            for (int nt = 0; nt < 8; ++nt) {
                int col = wn * 64 + nt * 8 + g;
                bh0[nt] = __float_as_uint(bh[(ks + tg) * BS_STR + col]);
                bh1[nt] = __float_as_uint(bh[(ks + tg + 4) * BS_STR + col]);
                bl0[nt] = __float_as_uint(bl[(ks + tg) * BS_STR + col]);
                bl1[nt] = __float_as_uint(bl[(ks + tg + 4) * BS_STR + col]);
            }
#pragma unroll
            for (int mt = 0; mt < 2; ++mt) {
                int row = wm * 32 + mt * 16 + g;
                float a0 = as[row * AS_STR + ks + tg];
                float a1 = as[(row + 8) * AS_STR + ks + tg];
                float a2 = as[row * AS_STR + ks + tg + 4];
                float a3 = as[(row + 8) * AS_STR + ks + tg + 4];
                uint32_t h0 = cvt_tf32(a0), h1 = cvt_tf32(a1);
                uint32_t h2 = cvt_tf32(a2), h3 = cvt_tf32(a3);
                uint32_t l0 = cvt_tf32(a0 - __uint_as_float(h0));
                uint32_t l1 = cvt_tf32(a1 - __uint_as_float(h1));
                uint32_t l2 = cvt_tf32(a2 - __uint_as_float(h2));
                uint32_t l3 = cvt_tf32(a3 - __uint_as_float(h3));
#pragma unroll
                for (int nt = 0; nt < 8; ++nt) {
                    MMA_TF32(acc[mt][nt], h0, h1, h2, h3, bh0[nt], bh1[nt]);
                    MMA_TF32(acc[mt][nt], h0, h1, h2, h3, bl0[nt], bl1[nt]);
                    MMA_TF32(acc[mt][nt], l0, l1, l2, l3, bh0[nt], bh1[nt]);
                }
            }
        }
    };

    // ---- main K loop: 16 k-blocks, double-buffered ----
    ldg_block(0);
    sts_block(0);
    __syncthreads();
#pragma unroll 1
    for (int kb = 0; kb < 16; ++kb) {
        if (kb < 15) ldg_block(kb + 1);
        compute(kb & 1);
        if (kb < 15) {
            sts_block((kb + 1) & 1);
            __syncthreads();
        }
    }

    // ---- epilogue: add bias, store ----
#pragma unroll
    for (int mt = 0; mt < 2; ++mt) {
        int row = m0 + wm * 32 + mt * 16 + g;
#pragma unroll
        for (int nt = 0; nt < 8; ++nt) {
            int col = n0 + wn * 64 + nt * 8 + tg * 2;
            float b0v = bias[col], b1v = bias[col + 1];
            *(float2*)(C + (size_t)row * H3 + col) =
                make_float2(acc[mt][nt][0] + b0v, acc[mt][nt][1] + b1v);
            *(float2*)(C + (size_t)(row + 8) * H3 + col) =
                make_float2(acc[mt][nt][2] + b0v, acc[mt][nt][3] + b1v);
        }
    }
}

// ---------------- persistent GRU recurrence (v5, unchanged from R13) ----------
__device__ __forceinline__ float fsig(float x)  { return 1.0f / (1.0f + __expf(-x)); }
__device__ __forceinline__ float ftanh(float x) { return 1.0f - 2.0f / (__expf(2.0f * x) + 1.0f); }

__global__ void __launch_bounds__(256, 1)
gru_recurrent(const float* __restrict__ xp, const float* __restrict__ brv) {
    extern __shared__ char sm[];
    float*  hs  = (float*)sm;                 // [512][64]
    float2* Rs  = (float2*)(sm + RS_OFF);
    ull*    red = (ull*)(sm + RED_OFF);
    __shared__ ull smb[2];

    const int tid  = threadIdx.x;
    const int half = tid >> 7;
    const int lt   = tid & 127;
    const int cpi  = lt >> 5;          // 0..3
    const int rp   = lt & 31;          // 0..31
    const int r0l  = rp * 2;           // local row
    const int blk  = blockIdx.x;
    const int cg   = blk >> 1;         // col-group
    const int bh   = blk & 1;          // batch half
    const int c0   = cg * 8 + 2 * cpi;
    const int gr0  = bh * 64 + r0l;    // global row

    uint32_t mbA = (uint32_t)__cvta_generic_to_shared(&smb[0]);
    uint32_t mbB = (uint32_t)__cvta_generic_to_shared(&smb[1]);
    uint32_t hsS = (uint32_t)__cvta_generic_to_shared(hs);
    if (tid == 0) { mbar_init(mbA, 1); mbar_init(mbB, 1); }

    // persistent paired R: 12 pair-rows (gate*4 + cpi) x 512 k
    for (int i = tid; i < 12 * 512; i += 256) {
        int L = i >> 9;
        int k = i & 511;
        int gate = L >> 2, cp = L & 3;
        int gp = gate * 256 + cg * 4 + cp;
        Rs[(size_t)L * 512 + k] = g_Rp[(size_t)gp * 512 + k];
    }

    const float2 bz2 = *(const float2*)(brv + c0);
    const float2 br2 = *(const float2*)(brv + HH + c0);
    const float2 bh2 = *(const float2*)(brv + 2 * HH + c0);

    // h_old carried in registers (h0 = 0)
    float hprev[2][2] = {{0.0f, 0.0f}, {0.0f, 0.0f}};

    const unsigned nCTA = gridDim.x;
    const uint32_t mywait = half ? mbB : mbA;
    __syncthreads();

    for (int t = 0; t < TT; ++t) {
        const float* hcur = (const float*)g_h2[t & 1][bh];
        float* hnx = (float*)g_h2[(t + 1) & 1][bh];

        // tid0 kicks off both bulk copies (slice is contiguous)
        if (tid == 0) {
            FENCE_PROXY();
            mbar_expect_tx(mbA, 65536u);
            bulk_g2s(hsS, hcur, 65536u, mbA);
            mbar_expect_tx(mbB, 65536u);
            bulk_g2s(hsS + 65536u, hcur + 16384, 65536u, mbB);
        }

        // prefetch xp gate inputs (latency overlaps bulk copy + compute)
        float2 xzp[2], xrp[2], xhp[2];
#pragma unroll
        for (int rr = 0; rr < 2; ++rr) {
            const float* xb = xp + ((size_t)(gr0 + rr) * TT + t) * H3;
            xzp[rr] = *(const float2*)(xb + c0);
            xrp[rr] = *(const float2*)(xb + HH + c0);
            xhp[rr] = *(const float2*)(xb + 2 * HH + c0);
        }

        // wait for this half's 64KB
        mbar_wait(mywait, (uint32_t)(t & 1));

        ull az0 = 0, az1 = 0, ar0 = 0, ar1 = 0, ah0 = 0, ah1 = 0;

        const float* hb = hs + (size_t)(half * 256) * 64;
        const int kg = half * 256;
        const float2* Rz = Rs + (size_t)(0 + cpi) * 512 + kg;
        const float2* Rr = Rs + (size_t)(4 + cpi) * 512 + kg;
        const float2* Rh = Rs + (size_t)(8 + cpi) * 512 + kg;

#pragma unroll 8
        for (int kk = 0; kk < 256; kk += 2) {
            ull hp0 = *(const ull*)(hb + (size_t)kk * 64 + r0l);
            ull hp1 = *(const ull*)(hb + (size_t)(kk + 1) * 64 + r0l);
            float h00, h01; unpack2(hp0, h00, h01);
            float h10, h11; unpack2(hp1, h10, h11);
            ull s00 = pack2(h00, h00), s01 = pack2(h01, h01);
            ull s10 = pack2(h10, h10), s11 = pack2(h11, h11);

            ulonglong2 vz = *(const ulonglong2*)(Rz + kk);
            ulonglong2 vr = *(const ulonglong2*)(Rr + kk);
            ulonglong2 vh = *(const ulonglong2*)(Rh + kk);

            az0 = ffma2(s00, vz.x, az0);  az1 = ffma2(s01, vz.x, az1);
            ar0 = ffma2(s00, vr.x, ar0);  ar1 = ffma2(s01, vr.x, ar1);
            ah0 = ffma2(s00, vh.x, ah0);  ah1 = ffma2(s01, vh.x, ah1);
            az0 = ffma2(s10, vz.y, az0);  az1 = ffma2(s11, vz.y, az1);
            ar0 = ffma2(s10, vr.y, ar0);  ar1 = ffma2(s11, vr.y, ar1);
            ah0 = ffma2(s10, vh.y, ah0);  ah1 = ffma2(s11, vh.y, ah1);
        }

        // K-split reduction: half 1 -> smem, half 0 accumulates + epilogue
        if (half) {
            ull* rd = red + (size_t)lt * 6;
            rd[0] = az0; rd[1] = az1; rd[2] = ar0;
            rd[3] = ar1; rd[4] = ah0; rd[5] = ah1;
        }
        __syncthreads();
        if (!half) {
            const ull* rd = red + (size_t)lt * 6;
            az0 = addx2(az0, rd[0]); az1 = addx2(az1, rd[1]);
            ar0 = addx2(ar0, rd[2]); ar1 = addx2(ar1, rd[3]);
            ah0 = addx2(ah0, rd[4]); ah1 = addx2(ah1, rd[5]);

            float azc[2][2], arc[2][2], ahc[2][2];
            unpack2(az0, azc[0][0], azc[0][1]);
            unpack2(az1, azc[1][0], azc[1][1]);
            unpack2(ar0, arc[0][0], arc[0][1]);
            unpack2(ar1, arc[1][0], arc[1][1]);
            unpack2(ah0, ahc[0][0], ahc[0][1]);
            unpack2(ah1, ahc[1][0], ahc[1][1]);

            float bzv[2]  = {bz2.x, bz2.y};
            float brvv[2] = {br2.x, br2.y};
            float bhv[2]  = {bh2.x, bh2.y};
#pragma unroll
            for (int rr = 0; rr < 2; ++rr) {
                float xzv[2] = {xzp[rr].x, xzp[rr].y};
                float xrv[2] = {xrp[rr].x, xrp[rr].y};
                float xhv[2] = {xhp[rr].x, xhp[rr].y};
#pragma unroll
                for (int cc = 0; cc < 2; ++cc) {
                    float z  = fsig(xzv[cc] + azc[rr][cc] + bzv[cc]);
                    float rg = fsig(xrv[cc] + arc[rr][cc] + brvv[cc]);
                    float hv = ftanh(xhv[cc] + rg * (ahc[rr][cc] + bhv[cc]));
                    hprev[rr][cc] = z * hprev[rr][cc] + (1.0f - z) * hv;
                }
            }
            *(float2*)(hnx + (size_t)c0 * 64 + r0l)       = make_float2(hprev[0][0], hprev[1][0]);
            *(float2*)(hnx + (size_t)(c0 + 1) * 64 + r0l) = make_float2(hprev[0][1], hprev[1][1]);
            __threadfence();
        }

        // grid barrier
        __syncthreads();
        if (tid == 0) {
            atomicAdd(&g_bar, 1u);
            unsigned target = nCTA * (unsigned)(t + 1);
            while (*(volatile unsigned*)&g_bar < target) { }
            __threadfence();
        }
        __syncthreads();
    }
}

// ---------------- final: logits = h_last @ Wf + bf ---------------------------
__global__ void final_logits(const float* __restrict__ Wf,
                             const float* __restrict__ bf,
                             float* __restrict__ out) {
    int tid = threadIdx.x;          // 256 threads: r = tid>>1, c = tid&1
    int r = tid >> 1;
    int c = tid & 1;
    const float* hsl = (const float*)g_h2[TT & 1][r >> 6];   // [k][64]
    int rl = r & 63;
    float acc = 0.0f;
    for (int k = 0; k < HH; ++k)
        acc += hsl[(size_t)k * 64 + rl] * Wf[k * NCLS + c];
    out[r * NCLS + c] = acc + bf[c];
}

// ---------------- launch -----------------------------------------------------
extern "C" void kernel_launch(void* const* d_in, const int* in_sizes, int n_in,
                              void* d_out, int out_size) {
    const float* x   = (const float*)d_in[0];
    const float* W   = (const float*)d_in[1];
    const float* R   = (const float*)d_in[2];
    const float* b_i = (const float*)d_in[3];
    const float* b_r = (const float*)d_in[4];
    const float* Wf  = (const float*)d_in[5];
    const float* bf  = (const float*)d_in[6];
    float* out = (float*)d_out;

    float* xp;
    cudaGetSymbolAddress((void**)&xp, g_xp);

    static bool attr_set = false;
    if (!attr_set) {
        cudaFuncSetAttribute(gru_recurrent,
                             cudaFuncAttributeMaxDynamicSharedMemorySize, SMEM_DYN);
        cudaFuncSetAttribute(gemm_tf32,
                             cudaFuncAttributeMaxDynamicSharedMemorySize, SMEMG);
        attr_set = true;
    }

    init_kernel<<<(2 * 512 * 64 + 255) / 256, 256>>>();
    build_Rp<<<(768 * 512 + 255) / 256, 256>>>(R);
    build_Whl<<<(DD * H3 + 255) / 256, 256>>>(W);
    {
        dim3 grid(H3 / 128, (BB * TT) / 128);   // (12, 1024)
        gemm_tf32<<<grid, 256, SMEMG>>>(x, b_i, xp);
    }
    gru_recurrent<<<128, 256, SMEM_DYN>>>(xp, b_r);
    final_logits<<<1, 256>>>(Wf, bf, out);
}

// round 15
// speedup vs baseline: 1.5276x; 1.0988x over previous
#include <cuda_runtime.h>
#include <math.h>
#include <stdint.h>

// Problem dims (fixed)
#define BB   128
#define TT   1024
#define DD   512
#define HH   512
#define H3   1536
#define NCLS 2

typedef unsigned long long ull;

// GEMM1 (tf32 mma) smem
#define AS_STR  36
#define BS_STR  136
#define AS_FL   (2 * 128 * AS_STR)
#define BH_FL   (2 * 32 * BS_STR)
#define SMEMG   ((AS_FL + 2 * BH_FL) * 4)  // 106496 bytes

// recurrence MMA smem: A frag tile 128KB + B frag tile 96KB
#define RA_B    131072                      // [4 m][64 kb][32 lane][4 frag] floats
#define RB_B    98304                       // [3 gate][64 kb][32 lane][4] floats
#define SMEM_R  (RA_B + RB_B)               // 229376 <= 232448

// ---------------- scratch ----------------------------------------------------
__device__ float  g_xp[(size_t)BB * TT * H3];   // [B*T, 3H], row m = b*T + t
__device__ float  g_Whi[DD * H3];
__device__ float  g_Wlo[DD * H3];
__device__ float4 g_Rf[64 * 3 * 64 * 32];       // [cg][gate][kb][lane] = (bh0,bh1,bl0,bl1)
__device__ float  g_hF[2][2][4][64][32][4];     // [buf][bh][m][kb][lane][frag]
__device__ unsigned int g_bar;

// ---------------- tf32 helpers -----------------------------------------------
__device__ __forceinline__ uint32_t cvt_tf32(float v) {
    uint32_t r; asm("cvt.rna.tf32.f32 %0, %1;" : "=r"(r) : "f"(v)); return r;
}
#define MMA_TF32(d, a0, a1, a2, a3, b0, b1) \
    asm volatile("mma.sync.aligned.m16n8k8.row.col.f32.tf32.tf32.f32 " \
        "{%0,%1,%2,%3}, {%4,%5,%6,%7}, {%8,%9}, {%0,%1,%2,%3};" \
        : "+f"((d)[0]), "+f"((d)[1]), "+f"((d)[2]), "+f"((d)[3]) \
        : "r"(a0), "r"(a1), "r"(a2), "r"(a3), "r"(b0), "r"(b1))

// ---------------- bulk-async + mbarrier helpers ------------------------------
__device__ __forceinline__ void mbar_init(uint32_t a, uint32_t cnt) {
    asm volatile("mbarrier.init.shared.b64 [%0], %1;" :: "r"(a), "r"(cnt) : "memory");
}
__device__ __forceinline__ void mbar_expect_tx(uint32_t a, uint32_t tx) {
    asm volatile("mbarrier.arrive.expect_tx.shared.b64 _, [%0], %1;"
                 :: "r"(a), "r"(tx) : "memory");
}
__device__ __forceinline__ void mbar_wait(uint32_t a, uint32_t parity) {
    asm volatile(
        "{\n\t"
        ".reg .pred P;\n\t"
        "WL%=:\n\t"
        "mbarrier.try_wait.parity.shared.b64 P, [%0], %1;\n\t"
        "@!P bra WL%=;\n\t"
        "}"
        :: "r"(a), "r"(parity) : "memory");
}
__device__ __forceinline__ void bulk_g2s(uint32_t dst, const void* src,
                                         uint32_t bytes, uint32_t mbar) {
    ull g;
    asm volatile("cvta.to.global.u64 %0, %1;" : "=l"(g) : "l"(src));
    asm volatile(
        "cp.async.bulk.shared::cluster.global.mbarrier::complete_tx::bytes "
        "[%0], [%1], %2, [%3];"
        :: "r"(dst), "l"(g), "r"(bytes), "r"(mbar) : "memory");
}
#define FENCE_PROXY() asm volatile("fence.proxy.async.shared::cta;" ::: "memory")

// ---------------- init -------------------------------------------------------
__global__ void init_kernel() {
    int idx = blockIdx.x * blockDim.x + threadIdx.x;
    if (idx == 0) g_bar = 0u;
    if (idx < 2 * 4 * 64 * 32 * 4) ((float*)g_hF[0])[idx] = 0.0f;
}

// ---------------- build W hi/lo tf32 split -----------------------------------
__global__ void build_Whl(const float* __restrict__ W) {
    int idx = blockIdx.x * blockDim.x + threadIdx.x;
    if (idx < DD * H3) {
        float v = W[idx];
        uint32_t h = cvt_tf32(v);
        float hf = __uint_as_float(h);
        g_Whi[idx] = hf;
        g_Wlo[idx] = __uint_as_float(cvt_tf32(v - hf));
    }
}

// ---------------- build fragment-ordered R (hi/lo) ---------------------------
// g_Rf[cg][gate][kb][lane] : lane = g*4+tg
//   .x = hi(R[kb*8+tg  ][gate*512 + cg*8 + g])
//   .y = hi(R[kb*8+tg+4][col]), .z = lo(k0), .w = lo(k1)
__global__ void build_Rf(const float* __restrict__ R) {
    int idx = blockIdx.x * blockDim.x + threadIdx.x;   // over 64*3*64*32
    if (idx < 64 * 3 * 64 * 32) {
        int lane = idx & 31;
        int kb   = (idx >> 5) & 63;
        int gate = (idx >> 11) % 3;
        int cg   = idx / (3 * 64 * 32);
        int g  = lane >> 2, tg = lane & 3;
        int col = gate * 512 + cg * 8 + g;
        float v0 = R[(size_t)(kb * 8 + tg) * H3 + col];
        float v1 = R[(size_t)(kb * 8 + tg + 4) * H3 + col];
        float h0 = __uint_as_float(cvt_tf32(v0));
        float h1 = __uint_as_float(cvt_tf32(v1));
        float l0 = __uint_as_float(cvt_tf32(v0 - h0));
        float l1 = __uint_as_float(cvt_tf32(v1 - h1));
        g_Rf[idx] = make_float4(h0, h1, l0, l1);
    }
}

// ---------------- GEMM1: xp = x @ W + b_i via 3xTF32 mma.sync (unchanged) ----
__global__ void __launch_bounds__(256, 1)
gemm_tf32(const float* __restrict__ A, const float* __restrict__ bias,
          float* __restrict__ C) {
    extern __shared__ float sg[];
    float* As = sg;
    float* Bh = sg + AS_FL;
    float* Bl = Bh + BH_FL;

    const int tid  = threadIdx.x;
    const int lane = tid & 31;
    const int wid  = tid >> 5;
    const int wm   = wid & 3;
    const int wn   = wid >> 2;
    const int g    = lane >> 2;
    const int tg   = lane & 3;
    const int m0   = blockIdx.y * 128;
    const int n0   = blockIdx.x * 128;

    const float* Whi = g_Whi;
    const float* Wlo = g_Wlo;

    float acc[2][8][4];
#pragma unroll
    for (int mt = 0; mt < 2; ++mt)
#pragma unroll
        for (int nt = 0; nt < 8; ++nt)
#pragma unroll
            for (int i = 0; i < 4; ++i) acc[mt][nt][i] = 0.0f;

    float4 ra[4], rbh[4], rbl[4];

    auto ldg_block = [&](int kb) {
        const int kbase = kb * 32;
#pragma unroll
        for (int i = 0; i < 4; ++i) {
            int f = tid + i * 256;
            int row = f >> 3, kq = f & 7;
            ra[i] = *(const float4*)(A + (size_t)(m0 + row) * DD + kbase + kq * 4);
        }
#pragma unroll
        for (int i = 0; i < 4; ++i) {
            int f = tid + i * 256;
            int kr = f >> 5, nq = f & 31;
            size_t off = (size_t)(kbase + kr) * H3 + n0 + nq * 4;
            rbh[i] = *(const float4*)(Whi + off);
            rbl[i] = *(const float4*)(Wlo + off);
        }
    };
    auto sts_block = [&](int buf) {
        float* as = As + buf * 128 * AS_STR;
        float* bh = Bh + buf * 32 * BS_STR;
        float* bl = Bl + buf * 32 * BS_STR;
#pragma unroll
        for (int i = 0; i < 4; ++i) {
            int f = tid + i * 256;
            int row = f >> 3, kq = f & 7;
            *(float4*)(as + row * AS_STR + kq * 4) = ra[i];
        }
#pragma unroll
        for (int i = 0; i < 4; ++i) {
            int f = tid + i * 256;
            int kr = f >> 5, nq = f & 31;
            *(float4*)(bh + kr * BS_STR + nq * 4) = rbh[i];
            *(float4*)(bl + kr * BS_STR + nq * 4) = rbl[i];
        }
    };
    auto compute = [&](int buf) {
        const float* as = As + buf * 128 * AS_STR;
        const float* bh = Bh + buf * 32 * BS_STR;
        const float* bl = Bl + buf * 32 * BS_STR;
#pragma unroll
        for (int ks = 0; ks < 32; ks += 8) {
            uint32_t bh0[8], bh1[8], bl0[8], bl1[8];
#pragma unroll
            for (int nt = 0; nt < 8; ++nt) {
                int col = wn * 64 + nt * 8 + g;
                bh0[nt] = __float_as_uint(bh[(ks + tg) * BS_STR + col]);
                bh1[nt] = __float_as_uint(bh[(ks + tg + 4) * BS_STR + col]);
                bl0[nt] = __float_as_uint(bl[(ks + tg) * BS_STR + col]);
                bl1[nt] = __float_as_uint(bl[(ks + tg + 4) * BS_STR + col]);
            }
#pragma unroll
            for (int mt = 0; mt < 2; ++mt) {
                int row = wm * 32 + mt * 16 + g;
                float a0 = as[row * AS_STR + ks + tg];
                float a1 = as[(row + 8) * AS_STR + ks + tg];
                float a2 = as[row * AS_STR + ks + tg + 4];
                float a3 = as[(row + 8) * AS_STR + ks + tg + 4];
                uint32_t h0 = cvt_tf32(a0), h1 = cvt_tf32(a1);
                uint32_t h2 = cvt_tf32(a2), h3 = cvt_tf32(a3);
                uint32_t l0 = cvt_tf32(a0 - __uint_as_float(h0));
                uint32_t l1 = cvt_tf32(a1 - __uint_as_float(h1));
                uint32_t l2 = cvt_tf32(a2 - __uint_as_float(h2));
                uint32_t l3 = cvt_tf32(a3 - __uint_as_float(h3));
#pragma unroll
                for (int nt = 0; nt < 8; ++nt) {
                    MMA_TF32(acc[mt][nt], h0, h1, h2, h3, bh0[nt], bh1[nt]);
                    MMA_TF32(acc[mt][nt], h0, h1, h2, h3, bl0[nt], bl1[nt]);
                    MMA_TF32(acc[mt][nt], l0, l1, l2, l3, bh0[nt], bh1[nt]);
                }
            }
        }
    };

    ldg_block(0);
    sts_block(0);
    __syncthreads();
#pragma unroll 1
    for (int kb = 0; kb < 16; ++kb) {
        if (kb < 15) ldg_block(kb + 1);
        compute(kb & 1);
        if (kb < 15) {
            sts_block((kb + 1) & 1);
            __syncthreads();
        }
    }

#pragma unroll
    for (int mt = 0; mt < 2; ++mt) {
        int row = m0 + wm * 32 + mt * 16 + g;
#pragma unroll
        for (int nt = 0; nt < 8; ++nt) {
            int col = n0 + wn * 64 + nt * 8 + tg * 2;
            float b0v = bias[col], b1v = bias[col + 1];
            *(float2*)(C + (size_t)row * H3 + col) =
                make_float2(acc[mt][nt][0] + b0v, acc[mt][nt][1] + b1v);
            *(float2*)(C + (size_t)(row + 8) * H3 + col) =
                make_float2(acc[mt][nt][2] + b0v, acc[mt][nt][3] + b1v);
        }
    }
}

// ---------------- recurrence: MMA tf32 (v6) -----------------------------------
// 128 CTAs = 64 col-groups x 2 batch halves; 128 threads = 4 warps (one m16 tile
// each, all 3 gates). h kept in GLOBAL in fragment order g_hF[buf][bh][m][kb][lane][frag]
// so the per-step bulk copy gives conflict-free LDS.128 A-fragments. R fragments
// (hi/lo packed) staged once. Epilogue fully thread-local; h_old in registers.
__device__ __forceinline__ float fsig(float x)  { return 1.0f / (1.0f + __expf(-x)); }
__device__ __forceinline__ float ftanh(float x) { return 1.0f - 2.0f / (__expf(2.0f * x) + 1.0f); }

__global__ void __launch_bounds__(128, 1)
gru_mma(const float* __restrict__ xp, const float* __restrict__ brv) {
    extern __shared__ char sm[];
    float4* As = (float4*)sm;                   // [4][64][32]
    float4* Bs = (float4*)(sm + RA_B);          // [3][64][32]
    __shared__ ull smb[2];

    const int tid  = threadIdx.x;
    const int lane = tid & 31;
    const int m    = tid >> 5;         // m16 tile 0..3
    const int g    = lane >> 2;        // 0..7
    const int tg   = lane & 3;         // 0..3
    const int blk  = blockIdx.x;
    const int cg   = blk >> 1;         // col-group (owns h cols cg*8..+7)
    const int bh   = blk & 1;          // batch half
    const int c0   = cg * 8 + tg * 2;  // this thread's first h col

    uint32_t mbA = (uint32_t)__cvta_generic_to_shared(&smb[0]);
    uint32_t mbB = (uint32_t)__cvta_generic_to_shared(&smb[1]);
    uint32_t asS = (uint32_t)__cvta_generic_to_shared(As);
    if (tid == 0) { mbar_init(mbA, 1); mbar_init(mbB, 1); }

    // stage fragment-ordered R (once)
    {
        const float4* src = g_Rf + (size_t)cg * (3 * 64 * 32);
        for (int i = tid; i < 3 * 64 * 32; i += 128) Bs[i] = src[i];
    }

    // biases for cols c0, c0+1
    float bzv[2] = {brv[c0], brv[c0 + 1]};
    float brg[2] = {brv[HH + c0], brv[HH + c0 + 1]};
    float bhv[2] = {brv[2 * HH + c0], brv[2 * HH + c0 + 1]};

    float hprev[2][2] = {{0.0f, 0.0f}, {0.0f, 0.0f}};   // [rowhalf][col]

    const unsigned nCTA = gridDim.x;
    const uint32_t mywait = (m < 2) ? mbA : mbB;
    __syncthreads();

    for (int t = 0; t < TT; ++t) {
        const float* src = (const float*)g_hF[t & 1][bh];
        float* dst = (float*)g_hF[(t + 1) & 1][bh];

        if (tid == 0) {
            FENCE_PROXY();
            mbar_expect_tx(mbA, 65536u);
            bulk_g2s(asS, src, 65536u, mbA);
            mbar_expect_tx(mbB, 65536u);
            bulk_g2s(asS + 65536u, src + 16384, 65536u, mbB);
        }

        // prefetch xp gate inputs (rows m*16+g (+8), cols c0..c0+1)
        float2 xz2[2], xr2[2], xh2[2];
#pragma unroll
        for (int hf = 0; hf < 2; ++hf) {
            int grow = bh * 64 + m * 16 + g + hf * 8;
            const float* xb = xp + ((size_t)grow * TT + t) * H3;
            xz2[hf] = *(const float2*)(xb + c0);
            xr2[hf] = *(const float2*)(xb + HH + c0);
            xh2[hf] = *(const float2*)(xb + 2 * HH + c0);
        }

        mbar_wait(mywait, (uint32_t)(t & 1));

        float acc[3][3][4];    // [gate][pass hh,hl,lh][4]
#pragma unroll
        for (int gt = 0; gt < 3; ++gt)
#pragma unroll
            for (int p = 0; p < 3; ++p)
#pragma unroll
                for (int i = 0; i < 4; ++i) acc[gt][p][i] = 0.0f;

        const float4* Am = As + m * (64 * 32);
#pragma unroll 2
        for (int kb = 0; kb < 64; ++kb) {
            float4 af = Am[kb * 32 + lane];
            uint32_t ah0 = cvt_tf32(af.x), ah1 = cvt_tf32(af.y);
            uint32_t ah2 = cvt_tf32(af.z), ah3 = cvt_tf32(af.w);
            uint32_t al0 = cvt_tf32(af.x - __uint_as_float(ah0));
            uint32_t al1 = cvt_tf32(af.y - __uint_as_float(ah1));
            uint32_t al2 = cvt_tf32(af.z - __uint_as_float(ah2));
            uint32_t al3 = cvt_tf32(af.w - __uint_as_float(ah3));
#pragma unroll
            for (int gt = 0; gt < 3; ++gt) {
                float4 bf = Bs[(gt * 64 + kb) * 32 + lane];
                uint32_t bh0 = __float_as_uint(bf.x), bh1 = __float_as_uint(bf.y);
                uint32_t bl0 = __float_as_uint(bf.z), bl1 = __float_as_uint(bf.w);
                MMA_TF32(acc[gt][0], ah0, ah1, ah2, ah3, bh0, bh1);
                MMA_TF32(acc[gt][1], ah0, ah1, ah2, ah3, bl0, bl1);
                MMA_TF32(acc[gt][2], al0, al1, al2, al3, bh0, bh1);
            }
        }

        // combine passes: az/ar/ah per frag elem i = rowhalf*2 + col
        float az[4], ar[4], ah[4];
#pragma unroll
        for (int i = 0; i < 4; ++i) {
            az[i] = acc[0][0][i] + acc[0][1][i] + acc[0][2][i];
            ar[i] = acc[1][0][i] + acc[1][1][i] + acc[1][2][i];
            ah[i] = acc[2][0][i] + acc[2][1][i] + acc[2][2][i];
        }

        // gates + write h_new into fragment-ordered global (next buffer)
#pragma unroll
        for (int hf = 0; hf < 2; ++hf) {
            float xzv[2] = {xz2[hf].x, xz2[hf].y};
            float xrv[2] = {xr2[hf].x, xr2[hf].y};
            float xhv[2] = {xh2[hf].x, xh2[hf].y};
#pragma unroll
            for (int cc = 0; cc < 2; ++cc) {
                int i = hf * 2 + cc;
                float z  = fsig(xzv[cc] + az[i] + bzv[cc]);
                float rg = fsig(xrv[cc] + ar[i] + brg[cc]);
                float hv = ftanh(xhv[cc] + rg * (ah[i] + bhv[cc]));
                hprev[hf][cc] = z * hprev[hf][cc] + (1.0f - z) * hv;
                int co   = tg * 2 + cc;
                int lnp  = g * 4 + (co & 3);
                int frag = hf + 2 * (tg >> 1);
                dst[(size_t)(((m * 64 + cg) * 32 + lnp) << 2) + frag] = hprev[hf][cc];
            }
        }
        __threadfence();

        // grid barrier
        __syncthreads();
        if (tid == 0) {
            atomicAdd(&g_bar, 1u);
            unsigned target = nCTA * (unsigned)(t + 1);
            while (*(volatile unsigned*)&g_bar < target) { }
            __threadfence();
        }
        __syncthreads();
    }
}

// ---------------- final: logits = h_last @ Wf + bf ----------------------------
__global__ void final_logits(const float* __restrict__ Wf,
                             const float* __restrict__ bf,
                             float* __restrict__ out) {
    int tid = threadIdx.x;          // 256 threads: r = tid>>1, c = tid&1
    int r = tid >> 1;
    int c = tid & 1;
    int bh = r >> 6, rl = r & 63;
    int m = rl >> 4, rt = rl & 15;
    int g = rt & 7, half = rt >> 3;
    const float* hb = (const float*)g_hF[TT & 1][bh];
    float acc = 0.0f;
    for (int k = 0; k < HH; ++k) {
        int kb = k >> 3, co = k & 7;
        int tg = co & 3, hi4 = co >> 2;
        float hval = hb[(size_t)(((m * 64 + kb) * 32 + g * 4 + tg) << 2) + half + 2 * hi4];
        acc += hval * Wf[k * NCLS + c];
    }
    out[r * NCLS + c] = acc + bf[c];
}

// ---------------- launch -------------------------------------------------------
extern "C" void kernel_launch(void* const* d_in, const int* in_sizes, int n_in,
                              void* d_out, int out_size) {
    const float* x   = (const float*)d_in[0];
    const float* W   = (const float*)d_in[1];
    const float* R   = (const float*)d_in[2];
    const float* b_i = (const float*)d_in[3];
    const float* b_r = (const float*)d_in[4];
    const float* Wf  = (const float*)d_in[5];
    const float* bf  = (const float*)d_in[6];
    float* out = (float*)d_out;

    float* xp;
    cudaGetSymbolAddress((void**)&xp, g_xp);

    static bool attr_set = false;
    if (!attr_set) {
        cudaFuncSetAttribute(gemm_tf32,
                             cudaFuncAttributeMaxDynamicSharedMemorySize, SMEMG);
        cudaFuncSetAttribute(gru_mma,
                             cudaFuncAttributeMaxDynamicSharedMemorySize, SMEM_R);
        attr_set = true;
    }

    init_kernel<<<(2 * 4 * 64 * 32 * 4 + 255) / 256, 256>>>();
    build_Whl<<<(DD * H3 + 255) / 256, 256>>>(W);
    build_Rf<<<(64 * 3 * 64 * 32 + 255) / 256, 256>>>(R);
    {
        dim3 grid(H3 / 128, (BB * TT) / 128);   // (12, 1024)
        gemm_tf32<<<grid, 256, SMEMG>>>(x, b_i, xp);
    }
    gru_mma<<<128, 128, SMEM_R>>>(xp, b_r);
    final_logits<<<1, 256>>>(Wf, bf, out);
}

// round 16
// speedup vs baseline: 1.7471x; 1.1437x over previous
#include <cuda_runtime.h>
#include <math.h>
#include <stdint.h>

// Problem dims (fixed)
#define BB   128
#define TT   1024
#define DD   512
#define HH   512
#define H3   1536
#define NCLS 2

typedef unsigned long long ull;

// GEMM1 (tf32 mma) smem
#define AS_STR  36
#define BS_STR  136
#define AS_FL   (2 * 128 * AS_STR)
#define BH_FL   (2 * 32 * BS_STR)
#define SMEMG   ((AS_FL + 2 * BH_FL) * 4)  // 106496 bytes

// recurrence MMA smem: A frag tile 128KB + B frag tile 96KB (red aliases As)
#define RA_B    131072                      // [4 m][64 kb][32 lane][4 frag] floats
#define RB_B    98304                       // [3 gate][64 kb][32 lane][4] floats
#define SMEM_R  (RA_B + RB_B)               // 229376 <= 232448

// ---------------- scratch ----------------------------------------------------
__device__ float  g_xp[(size_t)BB * TT * H3];   // [B*T, 3H], row m = b*T + t
__device__ float  g_Whi[DD * H3];
__device__ float  g_Wlo[DD * H3];
__device__ float4 g_Rf[64 * 3 * 64 * 32];       // [cg][gate][kb][lane] = (bh0,bh1,bl0,bl1)
__device__ float  g_hF[2][2][4][64][32][4];     // [buf][bh][m][kb][lane][frag]
__device__ unsigned int g_bar;

// ---------------- tf32 helpers -----------------------------------------------
__device__ __forceinline__ uint32_t cvt_tf32(float v) {
    uint32_t r; asm("cvt.rna.tf32.f32 %0, %1;" : "=r"(r) : "f"(v)); return r;
}
#define MMA_TF32(d, a0, a1, a2, a3, b0, b1) \
    asm volatile("mma.sync.aligned.m16n8k8.row.col.f32.tf32.tf32.f32 " \
        "{%0,%1,%2,%3}, {%4,%5,%6,%7}, {%8,%9}, {%0,%1,%2,%3};" \
        : "+f"((d)[0]), "+f"((d)[1]), "+f"((d)[2]), "+f"((d)[3]) \
        : "r"(a0), "r"(a1), "r"(a2), "r"(a3), "r"(b0), "r"(b1))

// ---------------- bulk-async + mbarrier helpers ------------------------------
__device__ __forceinline__ void mbar_init(uint32_t a, uint32_t cnt) {
    asm volatile("mbarrier.init.shared.b64 [%0], %1;" :: "r"(a), "r"(cnt) : "memory");
}
__device__ __forceinline__ void mbar_expect_tx(uint32_t a, uint32_t tx) {
    asm volatile("mbarrier.arrive.expect_tx.shared.b64 _, [%0], %1;"
                 :: "r"(a), "r"(tx) : "memory");
}
__device__ __forceinline__ void mbar_wait(uint32_t a, uint32_t parity) {
    asm volatile(
        "{\n\t"
        ".reg .pred P;\n\t"
        "WL%=:\n\t"
        "mbarrier.try_wait.parity.shared.b64 P, [%0], %1;\n\t"
        "@!P bra WL%=;\n\t"
        "}"
        :: "r"(a), "r"(parity) : "memory");
}
__device__ __forceinline__ void bulk_g2s(uint32_t dst, const void* src,
                                         uint32_t bytes, uint32_t mbar) {
    ull g;
    asm volatile("cvta.to.global.u64 %0, %1;" : "=l"(g) : "l"(src));
    asm volatile(
        "cp.async.bulk.shared::cluster.global.mbarrier::complete_tx::bytes "
        "[%0], [%1], %2, [%3];"
        :: "r"(dst), "l"(g), "r"(bytes), "r"(mbar) : "memory");
}
#define FENCE_PROXY() asm volatile("fence.proxy.async.shared::cta;" ::: "memory")

// ---------------- init -------------------------------------------------------
__global__ void init_kernel() {
    int idx = blockIdx.x * blockDim.x + threadIdx.x;
    if (idx == 0) g_bar = 0u;
    if (idx < 2 * 4 * 64 * 32 * 4) ((float*)g_hF[0])[idx] = 0.0f;
}

// ---------------- build W hi/lo tf32 split -----------------------------------
__global__ void build_Whl(const float* __restrict__ W) {
    int idx = blockIdx.x * blockDim.x + threadIdx.x;
    if (idx < DD * H3) {
        float v = W[idx];
        uint32_t h = cvt_tf32(v);
        float hf = __uint_as_float(h);
        g_Whi[idx] = hf;
        g_Wlo[idx] = __uint_as_float(cvt_tf32(v - hf));
    }
}

// ---------------- build fragment-ordered R (hi/lo) ---------------------------
__global__ void build_Rf(const float* __restrict__ R) {
    int idx = blockIdx.x * blockDim.x + threadIdx.x;   // over 64*3*64*32
    if (idx < 64 * 3 * 64 * 32) {
        int lane = idx & 31;
        int kb   = (idx >> 5) & 63;
        int gate = (idx >> 11) % 3;
        int cg   = idx / (3 * 64 * 32);
        int g  = lane >> 2, tg = lane & 3;
        int col = gate * 512 + cg * 8 + g;
        float v0 = R[(size_t)(kb * 8 + tg) * H3 + col];
        float v1 = R[(size_t)(kb * 8 + tg + 4) * H3 + col];
        float h0 = __uint_as_float(cvt_tf32(v0));
        float h1 = __uint_as_float(cvt_tf32(v1));
        float l0 = __uint_as_float(cvt_tf32(v0 - h0));
        float l1 = __uint_as_float(cvt_tf32(v1 - h1));
        g_Rf[idx] = make_float4(h0, h1, l0, l1);
    }
}

// ---------------- GEMM1: xp = x @ W + b_i via 3xTF32 mma.sync (unchanged) ----
__global__ void __launch_bounds__(256, 1)
gemm_tf32(const float* __restrict__ A, const float* __restrict__ bias,
          float* __restrict__ C) {
    extern __shared__ float sg[];
    float* As = sg;
    float* Bh = sg + AS_FL;
    float* Bl = Bh + BH_FL;

    const int tid  = threadIdx.x;
    const int lane = tid & 31;
    const int wid  = tid >> 5;
    const int wm   = wid & 3;
    const int wn   = wid >> 2;
    const int g    = lane >> 2;
    const int tg   = lane & 3;
    const int m0   = blockIdx.y * 128;
    const int n0   = blockIdx.x * 128;

    const float* Whi = g_Whi;
    const float* Wlo = g_Wlo;

    float acc[2][8][4];
#pragma unroll
    for (int mt = 0; mt < 2; ++mt)
#pragma unroll
        for (int nt = 0; nt < 8; ++nt)
#pragma unroll
            for (int i = 0; i < 4; ++i) acc[mt][nt][i] = 0.0f;

    float4 ra[4], rbh[4], rbl[4];

    auto ldg_block = [&](int kb) {
        const int kbase = kb * 32;
#pragma unroll
        for (int i = 0; i < 4; ++i) {
            int f = tid + i * 256;
            int row = f >> 3, kq = f & 7;
            ra[i] = *(const float4*)(A + (size_t)(m0 + row) * DD + kbase + kq * 4);
        }
#pragma unroll
        for (int i = 0; i < 4; ++i) {
            int f = tid + i * 256;
            int kr = f >> 5, nq = f & 31;
            size_t off = (size_t)(kbase + kr) * H3 + n0 + nq * 4;
            rbh[i] = *(const float4*)(Whi + off);
            rbl[i] = *(const float4*)(Wlo + off);
        }
    };
    auto sts_block = [&](int buf) {
        float* as = As + buf * 128 * AS_STR;
        float* bh = Bh + buf * 32 * BS_STR;
        float* bl = Bl + buf * 32 * BS_STR;
#pragma unroll
        for (int i = 0; i < 4; ++i) {
            int f = tid + i * 256;
            int row = f >> 3, kq = f & 7;
            *(float4*)(as + row * AS_STR + kq * 4) = ra[i];
        }
#pragma unroll
        for (int i = 0; i < 4; ++i) {
            int f = tid + i * 256;
            int kr = f >> 5, nq = f & 31;
            *(float4*)(bh + kr * BS_STR + nq * 4) = rbh[i];
            *(float4*)(bl + kr * BS_STR + nq * 4) = rbl[i];
        }
    };
    auto compute = [&](int buf) {
        const float* as = As + buf * 128 * AS_STR;
        const float* bh = Bh + buf * 32 * BS_STR;
        const float* bl = Bl + buf * 32 * BS_STR;
#pragma unroll
        for (int ks = 0; ks < 32; ks += 8) {
            uint32_t bh0[8], bh1[8], bl0[8], bl1[8];
#pragma unroll
            for (int nt = 0; nt < 8; ++nt) {
                int col = wn * 64 + nt * 8 + g;
                bh0[nt] = __float_as_uint(bh[(ks + tg) * BS_STR + col]);
                bh1[nt] = __float_as_uint(bh[(ks + tg + 4) * BS_STR + col]);
                bl0[nt] = __float_as_uint(bl[(ks + tg) * BS_STR + col]);
                bl1[nt] = __float_as_uint(bl[(ks + tg + 4) * BS_STR + col]);
            }
#pragma unroll
            for (int mt = 0; mt < 2; ++mt) {
                int row = wm * 32 + mt * 16 + g;
                float a0 = as[row * AS_STR + ks + tg];
                float a1 = as[(row + 8) * AS_STR + ks + tg];
                float a2 = as[row * AS_STR + ks + tg + 4];
                float a3 = as[(row + 8) * AS_STR + ks + tg + 4];
                uint32_t h0 = cvt_tf32(a0), h1 = cvt_tf32(a1);
                uint32_t h2 = cvt_tf32(a2), h3 = cvt_tf32(a3);
                uint32_t l0 = cvt_tf32(a0 - __uint_as_float(h0));
                uint32_t l1 = cvt_tf32(a1 - __uint_as_float(h1));
                uint32_t l2 = cvt_tf32(a2 - __uint_as_float(h2));
                uint32_t l3 = cvt_tf32(a3 - __uint_as_float(h3));
#pragma unroll
                for (int nt = 0; nt < 8; ++nt) {
                    MMA_TF32(acc[mt][nt], h0, h1, h2, h3, bh0[nt], bh1[nt]);
                    MMA_TF32(acc[mt][nt], h0, h1, h2, h3, bl0[nt], bl1[nt]);
                    MMA_TF32(acc[mt][nt], l0, l1, l2, l3, bh0[nt], bh1[nt]);
                }
            }
        }
    };

    ldg_block(0);
    sts_block(0);
    __syncthreads();
#pragma unroll 1
    for (int kb = 0; kb < 16; ++kb) {
        if (kb < 15) ldg_block(kb + 1);
        compute(kb & 1);
        if (kb < 15) {
            sts_block((kb + 1) & 1);
            __syncthreads();
        }
    }

#pragma unroll
    for (int mt = 0; mt < 2; ++mt) {
        int row = m0 + wm * 32 + mt * 16 + g;
#pragma unroll
        for (int nt = 0; nt < 8; ++nt) {
            int col = n0 + wn * 64 + nt * 8 + tg * 2;
            float b0v = bias[col], b1v = bias[col + 1];
            *(float2*)(C + (size_t)row * H3 + col) =
                make_float2(acc[mt][nt][0] + b0v, acc[mt][nt][1] + b1v);
            *(float2*)(C + (size_t)(row + 8) * H3 + col) =
                make_float2(acc[mt][nt][2] + b0v, acc[mt][nt][3] + b1v);
        }
    }
}

// ---------------- recurrence: MMA tf32 (v7: 8 warps, K-split, 4-chunk bulk) ---
// 128 CTAs = 64 col-groups x 2 batch halves; 256 threads = 8 warps (m, khalf).
// Warp (m,kh) computes kb in [kh*32, kh*32+32) for m-tile m, all 3 gates.
// A chunks (32KB each, = one m-tile) arrive via 4 bulk copies + 4 mbarriers so
// each warp starts as soon as ITS chunk lands. K-halves combined via a smem
// reduction aliased onto As[0..6656) (safe: all As reads done before the store,
// next bulk write gated by grid barrier + mbar). Epilogue identical to R15.
__device__ __forceinline__ float fsig(float x)  { return 1.0f / (1.0f + __expf(-x)); }
__device__ __forceinline__ float ftanh(float x) { return 1.0f - 2.0f / (__expf(2.0f * x) + 1.0f); }

__global__ void __launch_bounds__(256, 1)
gru_mma(const float* __restrict__ xp, const float* __restrict__ brv) {
    extern __shared__ char sm[];
    float4* As  = (float4*)sm;                   // [4][64][32]
    float4* Bs  = (float4*)(sm + RA_B);          // [3][64][32]
    float*  red = (float*)sm;                    // alias (used between syncs only)
    __shared__ ull smb[4];

    const int tid  = threadIdx.x;
    const int lane = tid & 31;
    const int w    = tid >> 5;
    const int m    = w >> 1;           // m16 tile 0..3
    const int kh   = w & 1;            // k half
    const int g    = lane >> 2;        // 0..7
    const int tg   = lane & 3;         // 0..3
    const int blk  = blockIdx.x;
    const int cg   = blk >> 1;         // col-group (owns h cols cg*8..+7)
    const int bh   = blk & 1;          // batch half
    const int c0   = cg * 8 + tg * 2;  // this thread's first h col

    uint32_t mb0 = (uint32_t)__cvta_generic_to_shared(&smb[0]);
    uint32_t asS = (uint32_t)__cvta_generic_to_shared(As);
    if (tid == 0) {
#pragma unroll
        for (int q = 0; q < 4; ++q) mbar_init(mb0 + q * 8, 1);
    }

    // stage fragment-ordered R (once)
    {
        const float4* src = g_Rf + (size_t)cg * (3 * 64 * 32);
        for (int i = tid; i < 3 * 64 * 32; i += 256) Bs[i] = src[i];
    }

    // biases for cols c0, c0+1
    float bzv[2] = {brv[c0], brv[c0 + 1]};
    float brg[2] = {brv[HH + c0], brv[HH + c0 + 1]};
    float bhv[2] = {brv[2 * HH + c0], brv[2 * HH + c0 + 1]};

    float hprev[2][2] = {{0.0f, 0.0f}, {0.0f, 0.0f}};   // [rowhalf][col] (kh0 only)

    const unsigned nCTA = gridDim.x;
    const uint32_t mymb = mb0 + m * 8;
    __syncthreads();

    for (int t = 0; t < TT; ++t) {
        const float* src = (const float*)g_hF[t & 1][bh];
        float* dst = (float*)g_hF[(t + 1) & 1][bh];

        if (tid == 0) {
            FENCE_PROXY();
#pragma unroll
            for (int q = 0; q < 4; ++q) {
                mbar_expect_tx(mb0 + q * 8, 32768u);
                bulk_g2s(asS + (uint32_t)q * 32768u, src + q * 8192, 32768u, mb0 + q * 8);
            }
        }

        // prefetch xp gate inputs (epilogue warps only)
        float2 xz2[2], xr2[2], xh2[2];
        if (!kh) {
#pragma unroll
            for (int hf = 0; hf < 2; ++hf) {
                int grow = bh * 64 + m * 16 + g + hf * 8;
                const float* xb = xp + ((size_t)grow * TT + t) * H3;
                xz2[hf] = *(const float2*)(xb + c0);
                xr2[hf] = *(const float2*)(xb + HH + c0);
                xh2[hf] = *(const float2*)(xb + 2 * HH + c0);
            }
        }

        // wait for this m-tile's 32KB
        mbar_wait(mymb, (uint32_t)(t & 1));

        float acc[3][3][4];    // [gate][pass hh,hl,lh][4]
#pragma unroll
        for (int gt = 0; gt < 3; ++gt)
#pragma unroll
            for (int p = 0; p < 3; ++p)
#pragma unroll
                for (int i = 0; i < 4; ++i) acc[gt][p][i] = 0.0f;

        const float4* Am = As + m * (64 * 32);
        const int kb0 = kh * 32;
#pragma unroll 2
        for (int kb = kb0; kb < kb0 + 32; ++kb) {
            float4 af = Am[kb * 32 + lane];
            uint32_t ah0 = cvt_tf32(af.x), ah1 = cvt_tf32(af.y);
            uint32_t ah2 = cvt_tf32(af.z), ah3 = cvt_tf32(af.w);
            uint32_t al0 = cvt_tf32(af.x - __uint_as_float(ah0));
            uint32_t al1 = cvt_tf32(af.y - __uint_as_float(ah1));
            uint32_t al2 = cvt_tf32(af.z - __uint_as_float(ah2));
            uint32_t al3 = cvt_tf32(af.w - __uint_as_float(ah3));
#pragma unroll
            for (int gt = 0; gt < 3; ++gt) {
                float4 bf = Bs[(gt * 64 + kb) * 32 + lane];
                uint32_t bh0 = __float_as_uint(bf.x), bh1 = __float_as_uint(bf.y);
                uint32_t bl0 = __float_as_uint(bf.z), bl1 = __float_as_uint(bf.w);
                MMA_TF32(acc[gt][0], ah0, ah1, ah2, ah3, bh0, bh1);
                MMA_TF32(acc[gt][1], ah0, ah1, ah2, ah3, bl0, bl1);
                MMA_TF32(acc[gt][2], al0, al1, al2, al3, bh0, bh1);
            }
        }

        // thread-local pass combine
        float az[4], ar[4], ah[4];
#pragma unroll
        for (int i = 0; i < 4; ++i) {
            az[i] = acc[0][0][i] + acc[0][1][i] + acc[0][2][i];
            ar[i] = acc[1][0][i] + acc[1][1][i] + acc[1][2][i];
            ah[i] = acc[2][0][i] + acc[2][1][i] + acc[2][2][i];
        }

        // K-half reduction via smem (stride 13 floats: bank-conflict-free)
        __syncthreads();                 // all As reads done -> red alias safe
        if (kh) {
            float* rd = red + (size_t)(m * 32 + lane) * 13;
#pragma unroll
            for (int i = 0; i < 4; ++i) {
                rd[i] = az[i]; rd[4 + i] = ar[i]; rd[8 + i] = ah[i];
            }
        }
        __syncthreads();
        if (!kh) {
            const float* rd = red + (size_t)(m * 32 + lane) * 13;
#pragma unroll
            for (int i = 0; i < 4; ++i) {
                az[i] += rd[i]; ar[i] += rd[4 + i]; ah[i] += rd[8 + i];
            }

            // gates + write h_new into fragment-ordered global (next buffer)
#pragma unroll
            for (int hf = 0; hf < 2; ++hf) {
                float xzv[2] = {xz2[hf].x, xz2[hf].y};
                float xrv[2] = {xr2[hf].x, xr2[hf].y};
                float xhv[2] = {xh2[hf].x, xh2[hf].y};
#pragma unroll
                for (int cc = 0; cc < 2; ++cc) {
                    int i = hf * 2 + cc;
                    float z  = fsig(xzv[cc] + az[i] + bzv[cc]);
                    float rg = fsig(xrv[cc] + ar[i] + brg[cc]);
                    float hv = ftanh(xhv[cc] + rg * (ah[i] + bhv[cc]));
                    hprev[hf][cc] = z * hprev[hf][cc] + (1.0f - z) * hv;
                    int co   = tg * 2 + cc;
                    int lnp  = g * 4 + (co & 3);
                    int frag = hf + 2 * (tg >> 1);
                    dst[(size_t)(((m * 64 + cg) * 32 + lnp) << 2) + frag] = hprev[hf][cc];
                }
            }
            __threadfence();
        }

        // grid barrier
        __syncthreads();
        if (tid == 0) {
            atomicAdd(&g_bar, 1u);
            unsigned target = nCTA * (unsigned)(t + 1);
            while (*(volatile unsigned*)&g_bar < target) { }
            __threadfence();
        }
        __syncthreads();
    }
}

// ---------------- final: logits = h_last @ Wf + bf ----------------------------
__global__ void final_logits(const float* __restrict__ Wf,
                             const float* __restrict__ bf,
                             float* __restrict__ out) {
    int tid = threadIdx.x;          // 256 threads: r = tid>>1, c = tid&1
    int r = tid >> 1;
    int c = tid & 1;
    int bh = r >> 6, rl = r & 63;
    int m = rl >> 4, rt = rl & 15;
    int g = rt & 7, half = rt >> 3;
    const float* hb = (const float*)g_hF[TT & 1][bh];
    float acc = 0.0f;
    for (int k = 0; k < HH; ++k) {
        int kb = k >> 3, co = k & 7;
        int tg = co & 3, hi4 = co >> 2;
        float hval = hb[(size_t)(((m * 64 + kb) * 32 + g * 4 + tg) << 2) + half + 2 * hi4];
        acc += hval * Wf[k * NCLS + c];
    }
    out[r * NCLS + c] = acc + bf[c];
}

// ---------------- launch -------------------------------------------------------
extern "C" void kernel_launch(void* const* d_in, const int* in_sizes, int n_in,
                              void* d_out, int out_size) {
    const float* x   = (const float*)d_in[0];
    const float* W   = (const float*)d_in[1];
    const float* R   = (const float*)d_in[2];
    const float* b_i = (const float*)d_in[3];
    const float* b_r = (const float*)d_in[4];
    const float* Wf  = (const float*)d_in[5];
    const float* bf  = (const float*)d_in[6];
    float* out = (float*)d_out;

    float* xp;
    cudaGetSymbolAddress((void**)&xp, g_xp);

    static bool attr_set = false;
    if (!attr_set) {
        cudaFuncSetAttribute(gemm_tf32,
                             cudaFuncAttributeMaxDynamicSharedMemorySize, SMEMG);
        cudaFuncSetAttribute(gru_mma,
                             cudaFuncAttributeMaxDynamicSharedMemorySize, SMEM_R);
        attr_set = true;
    }

    init_kernel<<<(2 * 4 * 64 * 32 * 4 + 255) / 256, 256>>>();
    build_Whl<<<(DD * H3 + 255) / 256, 256>>>(W);
    build_Rf<<<(64 * 3 * 64 * 32 + 255) / 256, 256>>>(R);
    {
        dim3 grid(H3 / 128, (BB * TT) / 128);   // (12, 1024)
        gemm_tf32<<<grid, 256, SMEMG>>>(x, b_i, xp);
    }
    gru_mma<<<128, 256, SMEM_R>>>(xp, b_r);
    final_logits<<<1, 256>>>(Wf, bf, out);
}

// round 17
// speedup vs baseline: 1.7990x; 1.0297x over previous
#include <cuda_runtime.h>
#include <math.h>
#include <stdint.h>

// Problem dims (fixed)
#define BB   128
#define TT   1024
#define DD   512
#define HH   512
#define H3   1536
#define NCLS 2

typedef unsigned long long ull;

// GEMM1 (tf32 mma) smem
#define AS_STR  36
#define BS_STR  136
#define AS_FL   (2 * 128 * AS_STR)
#define BH_FL   (2 * 32 * BS_STR)
#define SMEMG   ((AS_FL + 2 * BH_FL) * 4)  // 106496 bytes

// recurrence MMA smem: A frag tile 128KB + B frag tile 96KB (red aliases As)
#define RA_B    131072                      // [4 m][64 kb][32 lane][4 frag] floats
#define RB_B    98304                       // [3 gate][64 kb][32 lane][4] floats
#define SMEM_R  (RA_B + RB_B)               // 229376 <= 232448

// ---------------- scratch ----------------------------------------------------
__device__ float  g_xp[(size_t)BB * TT * H3];   // [B*T, 3H], row m = b*T + t
__device__ float  g_Whi[DD * H3];
__device__ float  g_Wlo[DD * H3];
__device__ float4 g_Rf[64 * 3 * 64 * 32];       // [cg][gate][kb][lane] = (bh0,bh1,bl0,bl1)
__device__ float  g_hF[2][2][4][64][32][4];     // [buf][bh][m][kb][lane][frag]
__device__ unsigned int g_bar;

// ---------------- tf32 helpers -----------------------------------------------
__device__ __forceinline__ uint32_t cvt_tf32(float v) {
    uint32_t r; asm("cvt.rna.tf32.f32 %0, %1;" : "=r"(r) : "f"(v)); return r;
}
#define MMA_TF32(d, a0, a1, a2, a3, b0, b1) \
    asm volatile("mma.sync.aligned.m16n8k8.row.col.f32.tf32.tf32.f32 " \
        "{%0,%1,%2,%3}, {%4,%5,%6,%7}, {%8,%9}, {%0,%1,%2,%3};" \
        : "+f"((d)[0]), "+f"((d)[1]), "+f"((d)[2]), "+f"((d)[3]) \
        : "r"(a0), "r"(a1), "r"(a2), "r"(a3), "r"(b0), "r"(b1))

// ---------------- bulk-async + mbarrier helpers ------------------------------
__device__ __forceinline__ void mbar_init(uint32_t a, uint32_t cnt) {
    asm volatile("mbarrier.init.shared.b64 [%0], %1;" :: "r"(a), "r"(cnt) : "memory");
}
__device__ __forceinline__ void mbar_expect_tx(uint32_t a, uint32_t tx) {
    asm volatile("mbarrier.arrive.expect_tx.shared.b64 _, [%0], %1;"
                 :: "r"(a), "r"(tx) : "memory");
}
__device__ __forceinline__ void mbar_wait(uint32_t a, uint32_t parity) {
    asm volatile(
        "{\n\t"
        ".reg .pred P;\n\t"
        "WL%=:\n\t"
        "mbarrier.try_wait.parity.shared.b64 P, [%0], %1;\n\t"
        "@!P bra WL%=;\n\t"
        "}"
        :: "r"(a), "r"(parity) : "memory");
}
__device__ __forceinline__ void bulk_g2s(uint32_t dst, const void* src,
                                         uint32_t bytes, uint32_t mbar) {
    ull g;
    asm volatile("cvta.to.global.u64 %0, %1;" : "=l"(g) : "l"(src));
    asm volatile(
        "cp.async.bulk.shared::cluster.global.mbarrier::complete_tx::bytes "
        "[%0], [%1], %2, [%3];"
        :: "r"(dst), "l"(g), "r"(bytes), "r"(mbar) : "memory");
}
#define FENCE_PROXY() asm volatile("fence.proxy.async.shared::cta;" ::: "memory")

// ---------------- init -------------------------------------------------------
__global__ void init_kernel() {
    int idx = blockIdx.x * blockDim.x + threadIdx.x;
    if (idx == 0) g_bar = 0u;
    if (idx < 2 * 4 * 64 * 32 * 4) ((float*)g_hF[0])[idx] = 0.0f;
}

// ---------------- build W hi/lo tf32 split -----------------------------------
__global__ void build_Whl(const float* __restrict__ W) {
    int idx = blockIdx.x * blockDim.x + threadIdx.x;
    if (idx < DD * H3) {
        float v = W[idx];
        uint32_t h = cvt_tf32(v);
        float hf = __uint_as_float(h);
        g_Whi[idx] = hf;
        g_Wlo[idx] = __uint_as_float(cvt_tf32(v - hf));
    }
}

// ---------------- build fragment-ordered R (hi/lo) ---------------------------
__global__ void build_Rf(const float* __restrict__ R) {
    int idx = blockIdx.x * blockDim.x + threadIdx.x;   // over 64*3*64*32
    if (idx < 64 * 3 * 64 * 32) {
        int lane = idx & 31;
        int kb   = (idx >> 5) & 63;
        int gate = (idx >> 11) % 3;
        int cg   = idx / (3 * 64 * 32);
        int g  = lane >> 2, tg = lane & 3;
        int col = gate * 512 + cg * 8 + g;
        float v0 = R[(size_t)(kb * 8 + tg) * H3 + col];
        float v1 = R[(size_t)(kb * 8 + tg + 4) * H3 + col];
        float h0 = __uint_as_float(cvt_tf32(v0));
        float h1 = __uint_as_float(cvt_tf32(v1));
        float l0 = __uint_as_float(cvt_tf32(v0 - h0));
        float l1 = __uint_as_float(cvt_tf32(v1 - h1));
        g_Rf[idx] = make_float4(h0, h1, l0, l1);
    }
}

// ---------------- GEMM1: xp = x @ W + b_i via 2xTF32 mma.sync ----------------
// 2-pass split: hh + hl (A residual pass dropped; ~2.4e-4 one-shot rel error
// on xp, damped by the GRU). Saves 1/3 of MMAs and the whole A-residual cvt chain.
__global__ void __launch_bounds__(256, 1)
gemm_tf32(const float* __restrict__ A, const float* __restrict__ bias,
          float* __restrict__ C) {
    extern __shared__ float sg[];
    float* As = sg;
    float* Bh = sg + AS_FL;
    float* Bl = Bh + BH_FL;

    const int tid  = threadIdx.x;
    const int lane = tid & 31;
    const int wid  = tid >> 5;
    const int wm   = wid & 3;
    const int wn   = wid >> 2;
    const int g    = lane >> 2;
    const int tg   = lane & 3;
    const int m0   = blockIdx.y * 128;
    const int n0   = blockIdx.x * 128;

    const float* Whi = g_Whi;
    const float* Wlo = g_Wlo;

    float acc[2][8][4];
#pragma unroll
    for (int mt = 0; mt < 2; ++mt)
#pragma unroll
        for (int nt = 0; nt < 8; ++nt)
#pragma unroll
            for (int i = 0; i < 4; ++i) acc[mt][nt][i] = 0.0f;

    float4 ra[4], rbh[4], rbl[4];

    auto ldg_block = [&](int kb) {
        const int kbase = kb * 32;
#pragma unroll
        for (int i = 0; i < 4; ++i) {
            int f = tid + i * 256;
            int row = f >> 3, kq = f & 7;
            ra[i] = *(const float4*)(A + (size_t)(m0 + row) * DD + kbase + kq * 4);
        }
#pragma unroll
        for (int i = 0; i < 4; ++i) {
            int f = tid + i * 256;
            int kr = f >> 5, nq = f & 31;
            size_t off = (size_t)(kbase + kr) * H3 + n0 + nq * 4;
            rbh[i] = *(const float4*)(Whi + off);
            rbl[i] = *(const float4*)(Wlo + off);
        }
    };
    auto sts_block = [&](int buf) {
        float* as = As + buf * 128 * AS_STR;
        float* bh = Bh + buf * 32 * BS_STR;
        float* bl = Bl + buf * 32 * BS_STR;
#pragma unroll
        for (int i = 0; i < 4; ++i) {
            int f = tid + i * 256;
            int row = f >> 3, kq = f & 7;
            *(float4*)(as + row * AS_STR + kq * 4) = ra[i];
        }
#pragma unroll
        for (int i = 0; i < 4; ++i) {
            int f = tid + i * 256;
            int kr = f >> 5, nq = f & 31;
            *(float4*)(bh + kr * BS_STR + nq * 4) = rbh[i];
            *(float4*)(bl + kr * BS_STR + nq * 4) = rbl[i];
        }
    };
    auto compute = [&](int buf) {
        const float* as = As + buf * 128 * AS_STR;
        const float* bh = Bh + buf * 32 * BS_STR;
        const float* bl = Bl + buf * 32 * BS_STR;
#pragma unroll
        for (int ks = 0; ks < 32; ks += 8) {
            uint32_t bh0[8], bh1[8], bl0[8], bl1[8];
#pragma unroll
            for (int nt = 0; nt < 8; ++nt) {
                int col = wn * 64 + nt * 8 + g;
                bh0[nt] = __float_as_uint(bh[(ks + tg) * BS_STR + col]);
                bh1[nt] = __float_as_uint(bh[(ks + tg + 4) * BS_STR + col]);
                bl0[nt] = __float_as_uint(bl[(ks + tg) * BS_STR + col]);
                bl1[nt] = __float_as_uint(bl[(ks + tg + 4) * BS_STR + col]);
            }
#pragma unroll
            for (int mt = 0; mt < 2; ++mt) {
                int row = wm * 32 + mt * 16 + g;
                float a0 = as[row * AS_STR + ks + tg];
                float a1 = as[(row + 8) * AS_STR + ks + tg];
                float a2 = as[row * AS_STR + ks + tg + 4];
                float a3 = as[(row + 8) * AS_STR + ks + tg + 4];
                uint32_t h0 = cvt_tf32(a0), h1 = cvt_tf32(a1);
                uint32_t h2 = cvt_tf32(a2), h3 = cvt_tf32(a3);
#pragma unroll
                for (int nt = 0; nt < 8; ++nt) {
                    MMA_TF32(acc[mt][nt], h0, h1, h2, h3, bh0[nt], bh1[nt]);
                    MMA_TF32(acc[mt][nt], h0, h1, h2, h3, bl0[nt], bl1[nt]);
                }
            }
        }
    };

    ldg_block(0);
    sts_block(0);
    __syncthreads();
#pragma unroll 1
    for (int kb = 0; kb < 16; ++kb) {
        if (kb < 15) ldg_block(kb + 1);
        compute(kb & 1);
        if (kb < 15) {
            sts_block((kb + 1) & 1);
            __syncthreads();
        }
    }

#pragma unroll
    for (int mt = 0; mt < 2; ++mt) {
        int row = m0 + wm * 32 + mt * 16 + g;
#pragma unroll
        for (int nt = 0; nt < 8; ++nt) {
            int col = n0 + wn * 64 + nt * 8 + tg * 2;
            float b0v = bias[col], b1v = bias[col + 1];
            *(float2*)(C + (size_t)row * H3 + col) =
                make_float2(acc[mt][nt][0] + b0v, acc[mt][nt][1] + b1v);
            *(float2*)(C + (size_t)(row + 8) * H3 + col) =
                make_float2(acc[mt][nt][2] + b0v, acc[mt][nt][3] + b1v);
        }
    }
}

// ---------------- recurrence: MMA tf32 (v7b: merged correction acc) -----------
// Same structure as R16 (passing): 8 warps (m, khalf), 4-chunk bulk pipeline,
// smem K-half reduce aliased on As. 3 tf32 passes kept for precision; the two
// correction passes (hl, lh) now accumulate into ONE register set.
__device__ __forceinline__ float fsig(float x)  { return 1.0f / (1.0f + __expf(-x)); }
__device__ __forceinline__ float ftanh(float x) { return 1.0f - 2.0f / (__expf(2.0f * x) + 1.0f); }

__global__ void __launch_bounds__(256, 1)
gru_mma(const float* __restrict__ xp, const float* __restrict__ brv) {
    extern __shared__ char sm[];
    float4* As  = (float4*)sm;                   // [4][64][32]
    float4* Bs  = (float4*)(sm + RA_B);          // [3][64][32]
    float*  red = (float*)sm;                    // alias (used between syncs only)
    __shared__ ull smb[4];

    const int tid  = threadIdx.x;
    const int lane = tid & 31;
    const int w    = tid >> 5;
    const int m    = w >> 1;           // m16 tile 0..3
    const int kh   = w & 1;            // k half
    const int g    = lane >> 2;        // 0..7
    const int tg   = lane & 3;         // 0..3
    const int blk  = blockIdx.x;
    const int cg   = blk >> 1;         // col-group (owns h cols cg*8..+7)
    const int bh   = blk & 1;          // batch half
    const int c0   = cg * 8 + tg * 2;  // this thread's first h col

    uint32_t mb0 = (uint32_t)__cvta_generic_to_shared(&smb[0]);
    uint32_t asS = (uint32_t)__cvta_generic_to_shared(As);
    if (tid == 0) {
#pragma unroll
        for (int q = 0; q < 4; ++q) mbar_init(mb0 + q * 8, 1);
    }

    // stage fragment-ordered R (once)
    {
        const float4* src = g_Rf + (size_t)cg * (3 * 64 * 32);
        for (int i = tid; i < 3 * 64 * 32; i += 256) Bs[i] = src[i];
    }

    // biases for cols c0, c0+1
    float bzv[2] = {brv[c0], brv[c0 + 1]};
    float brg[2] = {brv[HH + c0], brv[HH + c0 + 1]};
    float bhv[2] = {brv[2 * HH + c0], brv[2 * HH + c0 + 1]};

    float hprev[2][2] = {{0.0f, 0.0f}, {0.0f, 0.0f}};   // [rowhalf][col] (kh0 only)

    const unsigned nCTA = gridDim.x;
    const uint32_t mymb = mb0 + m * 8;
    __syncthreads();

    for (int t = 0; t < TT; ++t) {
        const float* src = (const float*)g_hF[t & 1][bh];
        float* dst = (float*)g_hF[(t + 1) & 1][bh];

        if (tid == 0) {
            FENCE_PROXY();
#pragma unroll
            for (int q = 0; q < 4; ++q) {
                mbar_expect_tx(mb0 + q * 8, 32768u);
                bulk_g2s(asS + (uint32_t)q * 32768u, src + q * 8192, 32768u, mb0 + q * 8);
            }
        }

        // prefetch xp gate inputs (epilogue warps only)
        float2 xz2[2], xr2[2], xh2[2];
        if (!kh) {
#pragma unroll
            for (int hf = 0; hf < 2; ++hf) {
                int grow = bh * 64 + m * 16 + g + hf * 8;
                const float* xb = xp + ((size_t)grow * TT + t) * H3;
                xz2[hf] = *(const float2*)(xb + c0);
                xr2[hf] = *(const float2*)(xb + HH + c0);
                xh2[hf] = *(const float2*)(xb + 2 * HH + c0);
            }
        }

        // wait for this m-tile's 32KB
        mbar_wait(mymb, (uint32_t)(t & 1));

        float acc[3][2][4];    // [gate][pass: hh | (hl+lh merged)][4]
#pragma unroll
        for (int gt = 0; gt < 3; ++gt)
#pragma unroll
            for (int p = 0; p < 2; ++p)
#pragma unroll
                for (int i = 0; i < 4; ++i) acc[gt][p][i] = 0.0f;

        const float4* Am = As + m * (64 * 32);
        const int kb0 = kh * 32;
#pragma unroll 2
        for (int kb = kb0; kb < kb0 + 32; ++kb) {
            float4 af = Am[kb * 32 + lane];
            uint32_t ah0 = cvt_tf32(af.x), ah1 = cvt_tf32(af.y);
            uint32_t ah2 = cvt_tf32(af.z), ah3 = cvt_tf32(af.w);
            uint32_t al0 = cvt_tf32(af.x - __uint_as_float(ah0));
            uint32_t al1 = cvt_tf32(af.y - __uint_as_float(ah1));
            uint32_t al2 = cvt_tf32(af.z - __uint_as_float(ah2));
            uint32_t al3 = cvt_tf32(af.w - __uint_as_float(ah3));
#pragma unroll
            for (int gt = 0; gt < 3; ++gt) {
                float4 bf = Bs[(gt * 64 + kb) * 32 + lane];
                uint32_t bh0 = __float_as_uint(bf.x), bh1 = __float_as_uint(bf.y);
                uint32_t bl0 = __float_as_uint(bf.z), bl1 = __float_as_uint(bf.w);
                MMA_TF32(acc[gt][0], ah0, ah1, ah2, ah3, bh0, bh1);
                MMA_TF32(acc[gt][1], ah0, ah1, ah2, ah3, bl0, bl1);
                MMA_TF32(acc[gt][1], al0, al1, al2, al3, bh0, bh1);
            }
        }

        // thread-local pass combine
        float az[4], ar[4], ah[4];
#pragma unroll
        for (int i = 0; i < 4; ++i) {
            az[i] = acc[0][0][i] + acc[0][1][i];
            ar[i] = acc[1][0][i] + acc[1][1][i];
            ah[i] = acc[2][0][i] + acc[2][1][i];
        }

        // K-half reduction via smem (stride 13 floats: bank-conflict-free)
        __syncthreads();                 // all As reads done -> red alias safe
        if (kh) {
            float* rd = red + (size_t)(m * 32 + lane) * 13;
#pragma unroll
            for (int i = 0; i < 4; ++i) {
                rd[i] = az[i]; rd[4 + i] = ar[i]; rd[8 + i] = ah[i];
            }
        }
        __syncthreads();
        if (!kh) {
            const float* rd = red + (size_t)(m * 32 + lane) * 13;
#pragma unroll
            for (int i = 0; i < 4; ++i) {
                az[i] += rd[i]; ar[i] += rd[4 + i]; ah[i] += rd[8 + i];
            }

            // gates + write h_new into fragment-ordered global (next buffer)
#pragma unroll
            for (int hf = 0; hf < 2; ++hf) {
                float xzv[2] = {xz2[hf].x, xz2[hf].y};
                float xrv[2] = {xr2[hf].x, xr2[hf].y};
                float xhv[2] = {xh2[hf].x, xh2[hf].y};
#pragma unroll
                for (int cc = 0; cc < 2; ++cc) {
                    int i = hf * 2 + cc;
                    float z  = fsig(xzv[cc] + az[i] + bzv[cc]);
                    float rg = fsig(xrv[cc] + ar[i] + brg[cc]);
                    float hv = ftanh(xhv[cc] + rg * (ah[i] + bhv[cc]));
                    hprev[hf][cc] = z * hprev[hf][cc] + (1.0f - z) * hv;
                    int co   = tg * 2 + cc;
                    int lnp  = g * 4 + (co & 3);
                    int frag = hf + 2 * (tg >> 1);
                    dst[(size_t)(((m * 64 + cg) * 32 + lnp) << 2) + frag] = hprev[hf][cc];
                }
            }
            __threadfence();
        }

        // grid barrier
        __syncthreads();
        if (tid == 0) {
            atomicAdd(&g_bar, 1u);
            unsigned target = nCTA * (unsigned)(t + 1);
            while (*(volatile unsigned*)&g_bar < target) { }
            __threadfence();
        }
        __syncthreads();
    }
}

// ---------------- final: logits = h_last @ Wf + bf ----------------------------
__global__ void final_logits(const float* __restrict__ Wf,
                             const float* __restrict__ bf,
                             float* __restrict__ out) {
    int tid = threadIdx.x;          // 256 threads: r = tid>>1, c = tid&1
    int r = tid >> 1;
    int c = tid & 1;
    int bh = r >> 6, rl = r & 63;
    int m = rl >> 4, rt = rl & 15;
    int g = rt & 7, half = rt >> 3;
    const float* hb = (const float*)g_hF[TT & 1][bh];
    float acc = 0.0f;
    for (int k = 0; k < HH; ++k) {
        int kb = k >> 3, co = k & 7;
        int tg = co & 3, hi4 = co >> 2;
        float hval = hb[(size_t)(((m * 64 + kb) * 32 + g * 4 + tg) << 2) + half + 2 * hi4];
        acc += hval * Wf[k * NCLS + c];
    }
    out[r * NCLS + c] = acc + bf[c];
}

// ---------------- launch -------------------------------------------------------
extern "C" void kernel_launch(void* const* d_in, const int* in_sizes, int n_in,
                              void* d_out, int out_size) {
    const float* x   = (const float*)d_in[0];
    const float* W   = (const float*)d_in[1];
    const float* R   = (const float*)d_in[2];
    const float* b_i = (const float*)d_in[3];
    const float* b_r = (const float*)d_in[4];
    const float* Wf  = (const float*)d_in[5];
    const float* bf  = (const float*)d_in[6];
    float* out = (float*)d_out;

    float* xp;
    cudaGetSymbolAddress((void**)&xp, g_xp);

    static bool attr_set = false;
    if (!attr_set) {
        cudaFuncSetAttribute(gemm_tf32,
                             cudaFuncAttributeMaxDynamicSharedMemorySize, SMEMG);
        cudaFuncSetAttribute(gru_mma,
                             cudaFuncAttributeMaxDynamicSharedMemorySize, SMEM_R);
        attr_set = true;
    }

    init_kernel<<<(2 * 4 * 64 * 32 * 4 + 255) / 256, 256>>>();
    build_Whl<<<(DD * H3 + 255) / 256, 256>>>(W);
    build_Rf<<<(64 * 3 * 64 * 32 + 255) / 256, 256>>>(R);
    {
        dim3 grid(H3 / 128, (BB * TT) / 128);   // (12, 1024)
        gemm_tf32<<<grid, 256, SMEMG>>>(x, b_i, xp);
    }
    gru_mma<<<128, 256, SMEM_R>>>(xp, b_r);
    final_logits<<<1, 256>>>(Wf, bf, out);
}